// round 5
// baseline (speedup 1.0000x reference)
#include <cuda_runtime.h>
#include <cuda_bf16.h>
#include <math.h>
#include <stdint.h>

#define S_LEN 2048
#define HID 2048
#define NK 16
#define NV 32
#define DK 128
#define DV 128
#define KSZ 4
#define CHUNK 64
#define NCHUNK (S_LEN / CHUNK)
#define KEY_DIM (NK * DK)          // 2048
#define VAL_DIM (NV * DV)          // 4096
#define CONV_DIM (2 * KEY_DIM + VAL_DIM)  // 8192

// ---------------- scratch (static device globals; no allocation) ----------------
__device__ float d_mixed[(size_t)S_LEN * CONV_DIM];   // pre-conv projections
__device__ float d_conv[(size_t)S_LEN * CONV_DIM];    // post conv + silu
__device__ float d_zbuf[(size_t)S_LEN * VAL_DIM];
__device__ float d_ab[(size_t)S_LEN * 128];           // a (cols 0-31) / b (cols 32-63) proj
__device__ float d_g[NV * S_LEN];                     // per-chunk cumsum'd gate, [h][s]
__device__ float d_beta[NV * S_LEN];                  // [h][s]
__device__ float d_qn[(size_t)S_LEN * NK * DK];       // l2norm(q) * DK^-0.5
__device__ float d_kn[(size_t)S_LEN * NK * DK];       // l2norm(k)
__device__ float d_u[(size_t)NV * S_LEN * DV];        // [h][s][dv]
__device__ float d_kcd[(size_t)NV * S_LEN * DK];      // [h][s][dk]
__device__ float d_scores[(size_t)NV * NCHUNK * CHUNK * CHUNK];
__device__ float d_o[(size_t)S_LEN * VAL_DIM];        // core output, [s][h*DV+dv]

// bf16 split buffers (hi/lo) for tensor-core GEMMs
__device__ __nv_bfloat16 d_xh[(size_t)S_LEN * HID];
__device__ __nv_bfloat16 d_xl[(size_t)S_LEN * HID];
__device__ __nv_bfloat16 d_wqh[(size_t)CONV_DIM * HID];
__device__ __nv_bfloat16 d_wql[(size_t)CONV_DIM * HID];
__device__ __nv_bfloat16 d_wzh[(size_t)VAL_DIM * HID];
__device__ __nv_bfloat16 d_wzl[(size_t)VAL_DIM * HID];
__device__ __nv_bfloat16 d_woh[(size_t)HID * VAL_DIM];
__device__ __nv_bfloat16 d_wol[(size_t)HID * VAL_DIM];
__device__ __nv_bfloat16 d_hh[(size_t)S_LEN * VAL_DIM];
__device__ __nv_bfloat16 d_hl[(size_t)S_LEN * VAL_DIM];
__device__ __nv_bfloat16 d_wabh[(size_t)128 * HID];   // packed W_a/W_b (zero padded)
__device__ __nv_bfloat16 d_wabl[(size_t)128 * HID];

// ================= helpers =================
__device__ __forceinline__ uint32_t smem_u32_of(const void* p) {
    uint32_t a;
    asm("{ .reg .u64 t; cvta.to.shared.u64 t, %1; cvt.u32.u64 %0, t; }" : "=r"(a) : "l"(p));
    return a;
}

#define LDMATRIX_X4(r0, r1, r2, r3, addr)                                        \
    asm volatile("ldmatrix.sync.aligned.m8n8.x4.shared.b16 {%0,%1,%2,%3}, [%4];" \
                 : "=r"(r0), "=r"(r1), "=r"(r2), "=r"(r3) : "r"(addr))

#define MMA_BF16(c, a, b)                                                        \
    asm volatile("mma.sync.aligned.m16n8k16.row.col.f32.bf16.bf16.f32 "          \
                 "{%0,%1,%2,%3}, {%4,%5,%6,%7}, {%8,%9}, {%0,%1,%2,%3};"         \
                 : "+f"((c)[0]), "+f"((c)[1]), "+f"((c)[2]), "+f"((c)[3])        \
                 : "r"((a)[0]), "r"((a)[1]), "r"((a)[2]), "r"((a)[3]),           \
                   "r"((b)[0]), "r"((b)[1]))

// =============== mma.sync bf16 3-term split GEMM: C[M,N] = A @ B^T ===============
// A: [M,K] hi/lo bf16 row-major; B: [N,K] hi/lo bf16 row-major; C fp32 row-major.
// Block tile 128x128, 8 warps (2x4), warp tile 64x32, BK=32.
// 3-stage cp.async pipeline: load for kt+2 issues at TOP of iter kt (its buffer
// was last read at kt-1), keeping 2 loads in flight under compute.
// SMEM rows padded to 40 bf16 (80B) -> conflict-free ldmatrix.
#define APAD 40
#define MAT_ELEMS (128 * APAD)            // 5120 per matrix
#define STAGE_ELEMS (4 * MAT_ELEMS)       // Ah, Al, Bh, Bl
#define NSTAGE 3
#define GEMM_SMEM (NSTAGE * STAGE_ELEMS * 2)   // 122880 bytes

__device__ __forceinline__ void stage_load(
    uint32_t stage_base_bytes,
    const __nv_bfloat16* __restrict__ Ah, const __nv_bfloat16* __restrict__ Al,
    const __nv_bfloat16* __restrict__ Bh, const __nv_bfloat16* __restrict__ Bl,
    int bm, int bn, int K, int k0, int tid) {
#pragma unroll
    for (int i = 0; i < 8; i++) {
        int id = tid + i * 256;        // 0..2047
        int mat = id >> 9;             // 0..3
        int rem = id & 511;
        int row = rem >> 2;            // 0..127
        int ch  = rem & 3;             // 16B chunk within 64B row
        const __nv_bfloat16* base = (mat == 0) ? Ah : (mat == 1) ? Al : (mat == 2) ? Bh : Bl;
        int grow = (mat < 2) ? (bm + row) : (bn + row);
        const __nv_bfloat16* g = base + (size_t)grow * K + k0 + ch * 8;
        uint32_t dst = stage_base_bytes + (uint32_t)(mat * MAT_ELEMS + row * APAD + ch * 8) * 2;
        asm volatile("cp.async.cg.shared.global [%0], [%1], 16;" :: "r"(dst), "l"(g) : "memory");
    }
    asm volatile("cp.async.commit_group;" ::: "memory");
}

__global__ __launch_bounds__(256, 1)
void gemm_mma(const __nv_bfloat16* __restrict__ Ah, const __nv_bfloat16* __restrict__ Al,
              const __nv_bfloat16* __restrict__ Bh, const __nv_bfloat16* __restrict__ Bl,
              float* __restrict__ C, int M, int N, int K) {
    extern __shared__ __nv_bfloat16 smB[];
    const int tid = threadIdx.x;
    const int lane = tid & 31;
    const int w = tid >> 5;
    const int wm = w >> 2;             // 0..1
    const int wn = w & 3;              // 0..3
    const int bm = blockIdx.y * 128, bn = blockIdx.x * 128;
    const uint32_t smb = smem_u32_of(smB);

    float acc[4][4][4];
#pragma unroll
    for (int mt = 0; mt < 4; mt++)
#pragma unroll
        for (int nt = 0; nt < 4; nt++)
#pragma unroll
            for (int r = 0; r < 4; r++) acc[mt][nt][r] = 0.f;

    // per-thread ldmatrix element offsets (within a matrix tile)
    const uint32_t aoff = (uint32_t)((wm * 64 + (lane & 15)) * APAD + (lane >> 4) * 8) * 2;
    const uint32_t boff = (uint32_t)((wn * 32 + ((lane >> 4) & 1) * 8 + (lane & 7)) * APAD
                                     + ((lane >> 3) & 1) * 8) * 2;

    const int nkt = K >> 5;
    stage_load(smb, Ah, Al, Bh, Bl, bm, bn, K, 0, tid);
    if (nkt > 1)
        stage_load(smb + STAGE_ELEMS * 2, Ah, Al, Bh, Bl, bm, bn, K, 32, tid);

    for (int kt = 0; kt < nkt; kt++) {
        // issue load for kt+2 into stage (kt+2)%3 (last read at kt-1; safe — barrier
        // at end of kt-1 has passed)
        if (kt + 2 < nkt) {
            int st = (kt + 2) % NSTAGE;
            stage_load(smb + (uint32_t)st * (STAGE_ELEMS * 2),
                       Ah, Al, Bh, Bl, bm, bn, K, (kt + 2) * 32, tid);
        }
        // wait for stage kt: pending groups after it = min(2, nkt-1-kt)
        if (kt + 3 <= nkt) {
            asm volatile("cp.async.wait_group 2;" ::: "memory");
        } else if (kt + 2 == nkt) {
            asm volatile("cp.async.wait_group 1;" ::: "memory");
        } else {
            asm volatile("cp.async.wait_group 0;" ::: "memory");
        }
        __syncthreads();

        uint32_t sb = smb + (uint32_t)(kt % NSTAGE) * (STAGE_ELEMS * 2);
        uint32_t sAh = sb + aoff;
        uint32_t sAl = sAh + MAT_ELEMS * 2;
        uint32_t sBh = sb + 2 * MAT_ELEMS * 2 + boff;
        uint32_t sBl = sBh + MAT_ELEMS * 2;

#pragma unroll
        for (int ks = 0; ks < 2; ks++) {
            uint32_t ah[4][4], al[4][4], bh[2][4], bl[2][4];
            uint32_t kadd = (uint32_t)(ks * 16) * 2;
#pragma unroll
            for (int mt = 0; mt < 4; mt++) {
                uint32_t ad = sAh + (uint32_t)(mt * 16 * APAD) * 2 + kadd;
                LDMATRIX_X4(ah[mt][0], ah[mt][1], ah[mt][2], ah[mt][3], ad);
                uint32_t ad2 = sAl + (uint32_t)(mt * 16 * APAD) * 2 + kadd;
                LDMATRIX_X4(al[mt][0], al[mt][1], al[mt][2], al[mt][3], ad2);
            }
#pragma unroll
            for (int bt = 0; bt < 2; bt++) {
                uint32_t bd = sBh + (uint32_t)(bt * 16 * APAD) * 2 + kadd;
                LDMATRIX_X4(bh[bt][0], bh[bt][1], bh[bt][2], bh[bt][3], bd);
                uint32_t bd2 = sBl + (uint32_t)(bt * 16 * APAD) * 2 + kadd;
                LDMATRIX_X4(bl[bt][0], bl[bt][1], bl[bt][2], bl[bt][3], bd2);
            }
#pragma unroll
            for (int mt = 0; mt < 4; mt++)
#pragma unroll
                for (int nt = 0; nt < 4; nt++) {
                    uint32_t bfh[2] = {bh[nt >> 1][(nt & 1) * 2], bh[nt >> 1][(nt & 1) * 2 + 1]};
                    uint32_t bfl[2] = {bl[nt >> 1][(nt & 1) * 2], bl[nt >> 1][(nt & 1) * 2 + 1]};
                    MMA_BF16(acc[mt][nt], ah[mt], bfh);
                    MMA_BF16(acc[mt][nt], ah[mt], bfl);
                    MMA_BF16(acc[mt][nt], al[mt], bfh);
                }
        }
        __syncthreads();
    }

    // epilogue: c-frag rows lane/4 (+8), cols (lane%4)*2 (+1)
    int r0 = bm + wm * 64 + (lane >> 2);
    int cc = bn + wn * 32 + (lane & 3) * 2;
#pragma unroll
    for (int mt = 0; mt < 4; mt++) {
#pragma unroll
        for (int nt = 0; nt < 4; nt++) {
            float* p0 = C + (size_t)(r0 + mt * 16) * N + cc + nt * 8;
            float* p1 = p0 + 8 * N;
            *(float2*)p0 = make_float2(acc[mt][nt][0], acc[mt][nt][1]);
            *(float2*)p1 = make_float2(acc[mt][nt][2], acc[mt][nt][3]);
        }
    }
}

// ---------------- fp32 -> bf16 hi/lo split ----------------
__global__ __launch_bounds__(256) void split_fp32(
    const float* __restrict__ src, __nv_bfloat16* __restrict__ hi,
    __nv_bfloat16* __restrict__ lo, int n4) {
    int i = blockIdx.x * 256 + threadIdx.x;
    if (i >= n4) return;
    float4 v = ((const float4*)src)[i];
    __nv_bfloat16 h0 = __float2bfloat16(v.x), h1 = __float2bfloat16(v.y);
    __nv_bfloat16 h2 = __float2bfloat16(v.z), h3 = __float2bfloat16(v.w);
    __nv_bfloat16 l0 = __float2bfloat16(v.x - __bfloat162float(h0));
    __nv_bfloat16 l1 = __float2bfloat16(v.y - __bfloat162float(h1));
    __nv_bfloat16 l2 = __float2bfloat16(v.z - __bfloat162float(h2));
    __nv_bfloat16 l3 = __float2bfloat16(v.w - __bfloat162float(h3));
    ((__nv_bfloat162*)hi)[2 * i]     = __nv_bfloat162(h0, h1);
    ((__nv_bfloat162*)hi)[2 * i + 1] = __nv_bfloat162(h2, h3);
    ((__nv_bfloat162*)lo)[2 * i]     = __nv_bfloat162(l0, l1);
    ((__nv_bfloat162*)lo)[2 * i + 1] = __nv_bfloat162(l2, l3);
}

// ---------------- pack W_a/W_b into zero-padded [128, HID] hi/lo ----------------
__global__ __launch_bounds__(256) void pack_ab(
    const float* __restrict__ Wa, const float* __restrict__ Wb) {
    int i = blockIdx.x * 256 + threadIdx.x;        // 128*HID
    if (i >= 128 * HID) return;
    int r = i >> 11;                               // HID = 2048
    float v = 0.f;
    if (r < 32) v = Wa[i - 0];                     // rows 0..31: W_a
    else if (r < 64) v = Wb[i - 32 * HID];         // rows 32..63: W_b
    __nv_bfloat16 h = __float2bfloat16(v);
    d_wabh[i] = h;
    d_wabl[i] = __float2bfloat16(v - __bfloat162float(h));
}

// ---------------- g/beta from ab projection ----------------
__global__ __launch_bounds__(256) void g_beta(
    const float* __restrict__ dt_bias, const float* __restrict__ A_log) {
    int i = blockIdx.x * 256 + threadIdx.x;        // S_LEN * 64
    int s = i >> 6, j = i & 63;
    float v = d_ab[(size_t)s * 128 + j];
    if (j < 32) {
        float xv = v + dt_bias[j];
        float sp = fmaxf(xv, 0.f) + log1pf(expf(-fabsf(xv)));  // stable softplus
        d_g[j * S_LEN + s] = -expf(A_log[j]) * sp;
    } else {
        d_beta[(j - 32) * S_LEN + s] = 1.f / (1.f + expf(-v));
    }
}

// ---------------- per-chunk inclusive cumsum of g ----------------
__global__ void g_cumsum() {
    int h = blockIdx.x >> 5;       // NCHUNK = 32
    int c = blockIdx.x & 31;
    __shared__ float buf[CHUNK];
    int i = threadIdx.x;
    buf[i] = d_g[h * S_LEN + c * CHUNK + i];
    __syncthreads();
#pragma unroll
    for (int off = 1; off < CHUNK; off <<= 1) {
        float v = (i >= off) ? buf[i - off] : 0.f;
        __syncthreads();
        buf[i] += v;
        __syncthreads();
    }
    d_g[h * S_LEN + c * CHUNK + i] = buf[i];
}

// ---------------- causal depthwise conv (K=4) + SiLU ----------------
__global__ __launch_bounds__(256) void conv_silu(const float* __restrict__ w) {
    int idx = blockIdx.x * 256 + threadIdx.x;  // S*CONV_DIM
    int c = idx % CONV_DIM;
    int s = idx / CONV_DIM;
    float acc = 0.f;
#pragma unroll
    for (int t = 0; t < KSZ; t++) {
        int sp = s - (KSZ - 1) + t;
        if (sp >= 0) acc += d_mixed[(size_t)sp * CONV_DIM + c] * w[c * KSZ + t];
    }
    d_conv[idx] = acc / (1.f + expf(-acc));  // silu
}

// ---------------- l2norm of q,k (16 source heads); q also * DK^-0.5 ----------------
__global__ __launch_bounds__(256) void qk_norm() {
    int gw = (blockIdx.x * 256 + threadIdx.x) >> 5;  // S*NK*2 warps
    int lane = threadIdx.x & 31;
    int which = gw & 1;                 // 0=q, 1=k
    int hk = (gw >> 1) & (NK - 1);
    int s = gw >> 5;
    const float* src = d_conv + (size_t)s * CONV_DIM + which * KEY_DIM + hk * DK + lane * 4;
    float4 v = *(const float4*)src;
    float ss = v.x * v.x + v.y * v.y + v.z * v.z + v.w * v.w;
#pragma unroll
    for (int o = 16; o; o >>= 1) ss += __shfl_xor_sync(0xffffffffu, ss, o);
    float r = rsqrtf(ss + 1e-6f);
    if (!which) r *= 0.08838834764831845f;  // DK^-0.5
    float* dst = (which ? d_kn : d_qn) + ((size_t)s * NK + hk) * DK + lane * 4;
    v.x *= r; v.y *= r; v.z *= r; v.w *= r;
    *(float4*)dst = v;
}

// ---------------- chunk-local: scores, UT transform, u, kcd ----------------
#define PADK 132
__global__ __launch_bounds__(256) void chunk_kernel() {
    int cid = blockIdx.x;
    int h = blockIdx.y;
    int h2 = h >> 1;                 // q/k source head (repeat ratio 2)
    int s0 = cid * CHUNK;
    extern __shared__ float smf[];
    float* Ks = smf;                   // 64*132 (normalized k)
    float* KBs = Ks + 64 * PADK;       // 64*132 (k*beta, later v*beta)
    float* Qs = KBs + 64 * PADK;       // 64*132
    float* Am = Qs + 64 * PADK;        // 64*64
    float* gc = Am + 64 * 64;          // 64
    float* bt = gc + 64;               // 64
    float* rowbuf = bt + 64;           // 64
    int tid = threadIdx.x;

    if (tid < 64) {
        gc[tid] = d_g[h * S_LEN + s0 + tid];
        bt[tid] = d_beta[h * S_LEN + s0 + tid];
    }
    __syncthreads();

    for (int t = tid; t < 64 * 32; t += 256) {
        int r = t >> 5, c4 = (t & 31) << 2;
        float4 kv = *(const float4*)&d_kn[((size_t)(s0 + r) * NK + h2) * DK + c4];
        float4 qv = *(const float4*)&d_qn[((size_t)(s0 + r) * NK + h2) * DK + c4];
        float b = bt[r];
        Ks[r * PADK + c4 + 0] = kv.x; Ks[r * PADK + c4 + 1] = kv.y;
        Ks[r * PADK + c4 + 2] = kv.z; Ks[r * PADK + c4 + 3] = kv.w;
        Qs[r * PADK + c4 + 0] = qv.x; Qs[r * PADK + c4 + 1] = qv.y;
        Qs[r * PADK + c4 + 2] = qv.z; Qs[r * PADK + c4 + 3] = qv.w;
        KBs[r * PADK + c4 + 0] = kv.x * b; KBs[r * PADK + c4 + 1] = kv.y * b;
        KBs[r * PADK + c4 + 2] = kv.z * b; KBs[r * PADK + c4 + 3] = kv.w * b;
    }
    __syncthreads();

    for (int t = tid; t < 4096; t += 256) {
        int i = t >> 6, j = t & 63;
        float sc = 0.f, am = 0.f;
        if (i >= j) {
            float dq = 0.f, dk = 0.f;
            const float* kr = Ks + j * PADK;
            const float* qr = Qs + i * PADK;
            const float* kbr = KBs + i * PADK;
#pragma unroll 4
            for (int d = 0; d < 128; d++) {
                float kj = kr[d];
                dq += qr[d] * kj;
                dk += kbr[d] * kj;
            }
            float e = expf(gc[i] - gc[j]);
            sc = dq * e;
            if (i > j) am = -dk * e;
        }
        d_scores[(size_t)(h * NCHUNK + cid) * 4096 + t] = sc;
        Am[t] = am;
    }
    __syncthreads();

    for (int i = 1; i < 64; i++) {
        if (tid < i) {
            int j = tid;
            float sum = Am[i * 64 + j];
            for (int k = j + 1; k < i; k++) sum += Am[i * 64 + k] * Am[k * 64 + j];
            rowbuf[j] = sum;
        }
        __syncthreads();
        if (tid < i) Am[i * 64 + tid] = rowbuf[tid];
        __syncthreads();
    }

    if (tid < 64) rowbuf[tid] = expf(gc[tid]);
    __syncthreads();
    for (int t = tid; t < 64 * 128; t += 256) {
        int r = t >> 7, d = t & 127;
        KBs[r * PADK + d] *= rowbuf[r];
    }
    __syncthreads();

    for (int t = tid; t < 8192; t += 256) {
        int i = t >> 7, dk = t & 127;
        float acc = KBs[i * PADK + dk];
        for (int j = 0; j < i; j++) acc += Am[i * 64 + j] * KBs[j * PADK + dk];
        d_kcd[((size_t)h * S_LEN + s0 + i) * DK + dk] = acc;
    }
    __syncthreads();

    for (int t = tid; t < 64 * 32; t += 256) {
        int r = t >> 5, c4 = (t & 31) << 2;
        float4 vv = *(const float4*)&d_conv[(size_t)(s0 + r) * CONV_DIM + 2 * KEY_DIM + h * DV + c4];
        float b = bt[r];
        KBs[r * PADK + c4 + 0] = vv.x * b; KBs[r * PADK + c4 + 1] = vv.y * b;
        KBs[r * PADK + c4 + 2] = vv.z * b; KBs[r * PADK + c4 + 3] = vv.w * b;
    }
    __syncthreads();

    for (int t = tid; t < 8192; t += 256) {
        int i = t >> 7, dv = t & 127;
        float acc = KBs[i * PADK + dv];
        for (int j = 0; j < i; j++) acc += Am[i * 64 + j] * KBs[j * PADK + dv];
        d_u[((size_t)h * S_LEN + s0 + i) * DV + dv] = acc;
    }
}

// ---------------- cross-chunk sequential state scan ----------------
__global__ __launch_bounds__(256) void scan_kernel() {
    int grp = blockIdx.x;
    int h = blockIdx.y;
    int h2 = h >> 1;
    int c0 = grp * 32;
    extern __shared__ float smf[];
    float* state = smf;                // 128*33
    float* T = state + 128 * 33;       // 64*132
    float* vnew = T + 64 * PADK;       // 64*33
    float* sc = vnew + 64 * 33;        // 64*64
    float* gc = sc + 4096;             // 64
    int tid = threadIdx.x;

    for (int t = tid; t < 128 * 33; t += 256) state[t] = 0.f;
    __syncthreads();

    for (int cid = 0; cid < NCHUNK; cid++) {
        int s0 = cid * CHUNK;
        if (tid < 64) gc[tid] = d_g[h * S_LEN + s0 + tid];
        __syncthreads();
        float gl = gc[63];

        for (int t = tid; t < 64 * 32; t += 256) {
            int r = t >> 5, c4 = (t & 31) << 2;
            float4 v = *(const float4*)&d_kcd[((size_t)h * S_LEN + s0 + r) * DK + c4];
            T[r * PADK + c4 + 0] = v.x; T[r * PADK + c4 + 1] = v.y;
            T[r * PADK + c4 + 2] = v.z; T[r * PADK + c4 + 3] = v.w;
        }
        __syncthreads();

        for (int t = tid; t < 2048; t += 256) {
            int c = t >> 5, j = t & 31;
            float acc = d_u[((size_t)h * S_LEN + s0 + c) * DV + c0 + j];
            const float* Tr = T + c * PADK;
#pragma unroll 4
            for (int d = 0; d < 128; d++) acc -= Tr[d] * state[d * 33 + j];
            vnew[c * 33 + j] = acc;
        }
        __syncthreads();

        for (int t = tid; t < 64 * 32; t += 256) {
            int r = t >> 5, c4 = (t & 31) << 2;
            float4 v = *(const float4*)&d_qn[((size_t)(s0 + r) * NK + h2) * DK + c4];
            float e = expf(gc[r]);
            T[r * PADK + c4 + 0] = v.x * e; T[r * PADK + c4 + 1] = v.y * e;
            T[r * PADK + c4 + 2] = v.z * e; T[r * PADK + c4 + 3] = v.w * e;
        }
        for (int t = tid; t < 4096; t += 256)
            sc[t] = d_scores[(size_t)(h * NCHUNK + cid) * 4096 + t];
        __syncthreads();

        for (int t = tid; t < 2048; t += 256) {
            int c = t >> 5, j = t & 31;
            float acc = 0.f;
            const float* Tr = T + c * PADK;
#pragma unroll 4
            for (int d = 0; d < 128; d++) acc += Tr[d] * state[d * 33 + j];
            const float* scr = sc + c * 64;
            for (int c2 = 0; c2 <= c; c2++) acc += scr[c2] * vnew[c2 * 33 + j];
            d_o[(size_t)(s0 + c) * VAL_DIM + h * DV + c0 + j] = acc;
        }
        __syncthreads();

        for (int t = tid; t < 64 * 32; t += 256) {
            int r = t >> 5, c4 = (t & 31) << 2;
            float4 v = *(const float4*)&d_kn[((size_t)(s0 + r) * NK + h2) * DK + c4];
            float e = expf(gl - gc[r]);
            T[r * PADK + c4 + 0] = v.x * e; T[r * PADK + c4 + 1] = v.y * e;
            T[r * PADK + c4 + 2] = v.z * e; T[r * PADK + c4 + 3] = v.w * e;
        }
        __syncthreads();

        float egl = expf(gl);
        for (int t = tid; t < 4096; t += 256) {
            int d = t >> 5, j = t & 31;
            float acc = state[d * 33 + j] * egl;
#pragma unroll 4
            for (int c = 0; c < 64; c++) acc += T[c * PADK + d] * vnew[c * 33 + j];
            state[d * 33 + j] = acc;
        }
        __syncthreads();
    }
}

// ---------------- RMS-norm + silu(z) gate -> bf16 hi/lo split ----------------
__global__ __launch_bounds__(256) void norm_gate(const float* __restrict__ norm_w) {
    int gw = (blockIdx.x * 256 + threadIdx.x) >> 5;  // S*NV rows
    int lane = threadIdx.x & 31;
    int s = gw >> 5;
    int h = gw & 31;
    size_t base = (size_t)s * VAL_DIM + h * DV + lane * 4;
    float4 v = *(const float4*)(d_o + base);
    float ss = v.x * v.x + v.y * v.y + v.z * v.z + v.w * v.w;
#pragma unroll
    for (int o = 16; o; o >>= 1) ss += __shfl_xor_sync(0xffffffffu, ss, o);
    float r = rsqrtf(ss * (1.f / 128.f) + 1e-6f);
    float4 z = *(const float4*)(d_zbuf + base);
    float4 w = *(const float4*)(norm_w + lane * 4);
    float o0 = v.x * r * w.x * (z.x / (1.f + expf(-z.x)));
    float o1 = v.y * r * w.y * (z.y / (1.f + expf(-z.y)));
    float o2 = v.z * r * w.z * (z.z / (1.f + expf(-z.z)));
    float o3 = v.w * r * w.w * (z.w / (1.f + expf(-z.w)));
    __nv_bfloat16 h0 = __float2bfloat16(o0), h1 = __float2bfloat16(o1);
    __nv_bfloat16 h2 = __float2bfloat16(o2), h3 = __float2bfloat16(o3);
    __nv_bfloat16 l0 = __float2bfloat16(o0 - __bfloat162float(h0));
    __nv_bfloat16 l1 = __float2bfloat16(o1 - __bfloat162float(h1));
    __nv_bfloat16 l2 = __float2bfloat16(o2 - __bfloat162float(h2));
    __nv_bfloat16 l3 = __float2bfloat16(o3 - __bfloat162float(h3));
    ((__nv_bfloat162*)d_hh)[base / 2]     = __nv_bfloat162(h0, h1);
    ((__nv_bfloat162*)d_hh)[base / 2 + 1] = __nv_bfloat162(h2, h3);
    ((__nv_bfloat162*)d_hl)[base / 2]     = __nv_bfloat162(l0, l1);
    ((__nv_bfloat162*)d_hl)[base / 2 + 1] = __nv_bfloat162(l2, l3);
}

// ---------------- launch ----------------
extern "C" void kernel_launch(void* const* d_in, const int* in_sizes, int n_in,
                              void* d_out, int out_size) {
    const float* x       = (const float*)d_in[0];
    const float* W_qkv   = (const float*)d_in[1];
    const float* W_z     = (const float*)d_in[2];
    const float* W_a     = (const float*)d_in[3];
    const float* W_b     = (const float*)d_in[4];
    const float* conv_w  = (const float*)d_in[5];
    const float* dt_bias = (const float*)d_in[6];
    const float* A_log   = (const float*)d_in[7];
    const float* norm_w  = (const float*)d_in[8];
    const float* W_out   = (const float*)d_in[9];
    float* out = (float*)d_out;

    void *p_mixed, *p_z, *p_ab, *p_xh, *p_xl, *p_wqh, *p_wql, *p_wzh, *p_wzl;
    void *p_woh, *p_wol, *p_hh, *p_hl, *p_wabh, *p_wabl;
    cudaGetSymbolAddress(&p_mixed, d_mixed);
    cudaGetSymbolAddress(&p_z, d_zbuf);
    cudaGetSymbolAddress(&p_ab, d_ab);
    cudaGetSymbolAddress(&p_xh, d_xh);   cudaGetSymbolAddress(&p_xl, d_xl);
    cudaGetSymbolAddress(&p_wqh, d_wqh); cudaGetSymbolAddress(&p_wql, d_wql);
    cudaGetSymbolAddress(&p_wzh, d_wzh); cudaGetSymbolAddress(&p_wzl, d_wzl);
    cudaGetSymbolAddress(&p_woh, d_woh); cudaGetSymbolAddress(&p_wol, d_wol);
    cudaGetSymbolAddress(&p_hh, d_hh);   cudaGetSymbolAddress(&p_hl, d_hl);
    cudaGetSymbolAddress(&p_wabh, d_wabh); cudaGetSymbolAddress(&p_wabl, d_wabl);

    int chunk_smem = (3 * 64 * PADK + 64 * 64 + 3 * 64) * (int)sizeof(float);
    int scan_smem  = (128 * 33 + 64 * PADK + 64 * 33 + 64 * 64 + 64) * (int)sizeof(float);
    cudaFuncSetAttribute(chunk_kernel, cudaFuncAttributeMaxDynamicSharedMemorySize, chunk_smem);
    cudaFuncSetAttribute(scan_kernel,  cudaFuncAttributeMaxDynamicSharedMemorySize, scan_smem);
    cudaFuncSetAttribute(gemm_mma,     cudaFuncAttributeMaxDynamicSharedMemorySize, GEMM_SMEM);

    // bf16 splits of GEMM operands (+ a/b weight pack)
    split_fp32<<<(S_LEN * HID / 4 + 255) / 256, 256>>>(x, (__nv_bfloat16*)p_xh, (__nv_bfloat16*)p_xl, S_LEN * HID / 4);
    split_fp32<<<(CONV_DIM * HID / 4 + 255) / 256, 256>>>(W_qkv, (__nv_bfloat16*)p_wqh, (__nv_bfloat16*)p_wql, CONV_DIM * HID / 4);
    split_fp32<<<(VAL_DIM * HID / 4 + 255) / 256, 256>>>(W_z, (__nv_bfloat16*)p_wzh, (__nv_bfloat16*)p_wzl, VAL_DIM * HID / 4);
    split_fp32<<<(HID * VAL_DIM / 4 + 255) / 256, 256>>>(W_out, (__nv_bfloat16*)p_woh, (__nv_bfloat16*)p_wol, HID * VAL_DIM / 4);
    pack_ab<<<(128 * HID + 255) / 256, 256>>>(W_a, W_b);

    // projections via tensor-core split GEMM (mma.sync)
    gemm_mma<<<dim3(CONV_DIM / 128, S_LEN / 128), 256, GEMM_SMEM>>>(
        (const __nv_bfloat16*)p_xh, (const __nv_bfloat16*)p_xl,
        (const __nv_bfloat16*)p_wqh, (const __nv_bfloat16*)p_wql,
        (float*)p_mixed, S_LEN, CONV_DIM, HID);
    gemm_mma<<<dim3(VAL_DIM / 128, S_LEN / 128), 256, GEMM_SMEM>>>(
        (const __nv_bfloat16*)p_xh, (const __nv_bfloat16*)p_xl,
        (const __nv_bfloat16*)p_wzh, (const __nv_bfloat16*)p_wzl,
        (float*)p_z, S_LEN, VAL_DIM, HID);
    gemm_mma<<<dim3(1, S_LEN / 128), 256, GEMM_SMEM>>>(
        (const __nv_bfloat16*)p_xh, (const __nv_bfloat16*)p_xl,
        (const __nv_bfloat16*)p_wabh, (const __nv_bfloat16*)p_wabl,
        (float*)p_ab, S_LEN, 128, HID);
    g_beta<<<(S_LEN * 64) / 256, 256>>>(dt_bias, A_log);
    g_cumsum<<<NV * NCHUNK, CHUNK>>>();

    conv_silu<<<(S_LEN * CONV_DIM) / 256, 256>>>(conv_w);
    qk_norm<<<(S_LEN * NK * 2) / 8, 256>>>();

    chunk_kernel<<<dim3(NCHUNK, NV), 256, chunk_smem>>>();
    scan_kernel<<<dim3(4, NV), 256, scan_smem>>>();

    norm_gate<<<(S_LEN * NV) / 8, 256>>>(norm_w);
    gemm_mma<<<dim3(HID / 128, S_LEN / 128), 256, GEMM_SMEM>>>(
        (const __nv_bfloat16*)p_hh, (const __nv_bfloat16*)p_hl,
        (const __nv_bfloat16*)p_woh, (const __nv_bfloat16*)p_wol,
        out, S_LEN, HID, VAL_DIM);
}

// round 7
// speedup vs baseline: 1.2030x; 1.2030x over previous
#include <cuda_runtime.h>
#include <cuda_bf16.h>
#include <math.h>
#include <stdint.h>

#define S_LEN 2048
#define HID 2048
#define NK 16
#define NV 32
#define DK 128
#define DV 128
#define KSZ 4
#define CHUNK 64
#define NCHUNK (S_LEN / CHUNK)
#define KEY_DIM (NK * DK)          // 2048
#define VAL_DIM (NV * DV)          // 4096
#define CONV_DIM (2 * KEY_DIM + VAL_DIM)  // 8192

// ---------------- scratch (static device globals; no allocation) ----------------
__device__ float d_mixed[(size_t)S_LEN * CONV_DIM];   // pre-conv projections
__device__ float d_conv[(size_t)S_LEN * CONV_DIM];    // post conv + silu
__device__ float d_zbuf[(size_t)S_LEN * VAL_DIM];
__device__ float d_ab[(size_t)S_LEN * 128];           // staging for Wab + a/b proj output
__device__ float d_g[NV * S_LEN];
__device__ float d_beta[NV * S_LEN];
__device__ float d_qn[(size_t)S_LEN * NK * DK];
__device__ float d_kn[(size_t)S_LEN * NK * DK];
__device__ float d_u[(size_t)NV * S_LEN * DV];
__device__ float d_kcd[(size_t)NV * S_LEN * DK];
__device__ float d_scores[(size_t)NV * NCHUNK * CHUNK * CHUNK];
__device__ float d_o[(size_t)S_LEN * VAL_DIM];
__device__ float d_hbuf[(size_t)S_LEN * VAL_DIM];

// int8 2-slice buffers + per-row scales
__device__ int8_t d_x1[(size_t)S_LEN * HID];
__device__ int8_t d_x2[(size_t)S_LEN * HID];
__device__ float  d_sx[S_LEN];
__device__ int8_t d_wq1[(size_t)CONV_DIM * HID];
__device__ int8_t d_wq2[(size_t)CONV_DIM * HID];
__device__ float  d_swq[CONV_DIM];
__device__ int8_t d_wz1[(size_t)VAL_DIM * HID];
__device__ int8_t d_wz2[(size_t)VAL_DIM * HID];
__device__ float  d_swz[VAL_DIM];
__device__ int8_t d_wo1[(size_t)HID * VAL_DIM];
__device__ int8_t d_wo2[(size_t)HID * VAL_DIM];
__device__ float  d_swo[HID];
__device__ int8_t d_h1[(size_t)S_LEN * VAL_DIM];
__device__ int8_t d_h2[(size_t)S_LEN * VAL_DIM];
__device__ float  d_sh[S_LEN];
__device__ int8_t d_wab1[(size_t)128 * HID];
__device__ int8_t d_wab2[(size_t)128 * HID];
__device__ float  d_swab[128];

// ================= helpers =================
__device__ __forceinline__ uint32_t smem_u32_of(const void* p) {
    uint32_t a;
    asm("{ .reg .u64 t; cvta.to.shared.u64 t, %1; cvt.u32.u64 %0, t; }" : "=r"(a) : "l"(p));
    return a;
}

#define LDMATRIX_X4(r0, r1, r2, r3, addr)                                        \
    asm volatile("ldmatrix.sync.aligned.m8n8.x4.shared.b16 {%0,%1,%2,%3}, [%4];" \
                 : "=r"(r0), "=r"(r1), "=r"(r2), "=r"(r3) : "r"(addr))

#define MMA_S8(c, a, b0v, b1v)                                                   \
    asm volatile("mma.sync.aligned.m16n8k32.row.col.s32.s8.s8.s32 "              \
                 "{%0,%1,%2,%3}, {%4,%5,%6,%7}, {%8,%9}, {%0,%1,%2,%3};"         \
                 : "+r"((c)[0]), "+r"((c)[1]), "+r"((c)[2]), "+r"((c)[3])        \
                 : "r"((a)[0]), "r"((a)[1]), "r"((a)[2]), "r"((a)[3]),           \
                   "r"(b0v), "r"(b1v))

// =============== int8 2-slice split GEMM: C[M,N] = A @ B^T ===============
// A ~ sa_i*(A1 + A2/256); B ~ sb_j*(B1 + B2/256).
// C = sa_i*sb_j*(P1 + (P2+P3)/256), P1=A1B1, P2=A1B2, P3=A2B1 (exact s32 accum).
// Block 128x128, 8 warps (2x4), warp 64x32, BK=64 bytes, 3-stage cp.async.
// SMEM rows padded to 80B -> conflict-free ldmatrix.
#define IPAD 80
#define IMATB (128 * IPAD)             // 10240 B per matrix
#define ISTAGEB (4 * IMATB)            // A1, A2, B1, B2 = 40960 B
#define INSTAGE 3
#define IGEMM_SMEM (INSTAGE * ISTAGEB) // 122880 B

__device__ __forceinline__ void stage_load_i8(
    uint32_t stage_base,
    const int8_t* __restrict__ A1, const int8_t* __restrict__ A2,
    const int8_t* __restrict__ B1, const int8_t* __restrict__ B2,
    int bm, int bn, int K, int k0, int tid) {
#pragma unroll
    for (int i = 0; i < 8; i++) {
        int id = tid + i * 256;        // 0..2047
        int mat = id >> 9;             // 0..3
        int rem = id & 511;
        int row = rem >> 2;            // 0..127
        int ch  = rem & 3;             // 16B chunk within 64B row
        const int8_t* base = (mat == 0) ? A1 : (mat == 1) ? A2 : (mat == 2) ? B1 : B2;
        int grow = (mat < 2) ? (bm + row) : (bn + row);
        const int8_t* g = base + (size_t)grow * K + k0 + ch * 16;
        uint32_t dst = stage_base + (uint32_t)(mat * IMATB + row * IPAD + ch * 16);
        asm volatile("cp.async.cg.shared.global [%0], [%1], 16;" :: "r"(dst), "l"(g) : "memory");
    }
    asm volatile("cp.async.commit_group;" ::: "memory");
}

__global__ __launch_bounds__(256, 1)
void gemm_i8(const int8_t* __restrict__ A1, const int8_t* __restrict__ A2,
             const int8_t* __restrict__ B1, const int8_t* __restrict__ B2,
             const float* __restrict__ sa, const float* __restrict__ sb,
             float* __restrict__ C, int M, int N, int K) {
    extern __shared__ char smI[];
    const int tid = threadIdx.x;
    const int lane = tid & 31;
    const int w = tid >> 5;
    const int wm = w >> 2;             // 0..1
    const int wn = w & 3;              // 0..3
    const int bm = blockIdx.y * 128, bn = blockIdx.x * 128;
    const uint32_t smb = smem_u32_of(smI);

    int hi[4][4][4], mid[4][4][4];
#pragma unroll
    for (int mt = 0; mt < 4; mt++)
#pragma unroll
        for (int nt = 0; nt < 4; nt++)
#pragma unroll
            for (int r = 0; r < 4; r++) { hi[mt][nt][r] = 0; mid[mt][nt][r] = 0; }

    // ldmatrix byte offsets within a matrix region
    const uint32_t aoff = (uint32_t)((wm * 64 + (lane & 15)) * IPAD + (lane >> 4) * 16);
    const uint32_t boff = (uint32_t)((wn * 32 + (lane & 15)) * IPAD + (lane >> 4) * 16);

    const int nkt = K >> 6;            // BK = 64 bytes
    stage_load_i8(smb, A1, A2, B1, B2, bm, bn, K, 0, tid);
    if (nkt > 1)
        stage_load_i8(smb + ISTAGEB, A1, A2, B1, B2, bm, bn, K, 64, tid);

    for (int kt = 0; kt < nkt; kt++) {
        if (kt + 2 < nkt) {
            int st = (kt + 2) % INSTAGE;
            stage_load_i8(smb + (uint32_t)st * ISTAGEB, A1, A2, B1, B2, bm, bn, K, (kt + 2) * 64, tid);
        }
        if (kt + 3 <= nkt) {
            asm volatile("cp.async.wait_group 2;" ::: "memory");
        } else if (kt + 2 == nkt) {
            asm volatile("cp.async.wait_group 1;" ::: "memory");
        } else {
            asm volatile("cp.async.wait_group 0;" ::: "memory");
        }
        __syncthreads();

        uint32_t sb0 = smb + (uint32_t)(kt % INSTAGE) * ISTAGEB;
        uint32_t sA1 = sb0 + aoff;
        uint32_t sA2 = sA1 + IMATB;
        uint32_t sB1 = sb0 + 2 * IMATB + boff;
        uint32_t sB2 = sB1 + IMATB;

#pragma unroll
        for (int ks = 0; ks < 2; ks++) {           // two k32 steps per 64B chunk
            uint32_t a1[4][4], a2[4][4], b1[2][4], b2[2][4];
            uint32_t kadd = (uint32_t)(ks * 32);
#pragma unroll
            for (int mt = 0; mt < 4; mt++) {
                uint32_t ad = sA1 + (uint32_t)(mt * 16 * IPAD) + kadd;
                LDMATRIX_X4(a1[mt][0], a1[mt][1], a1[mt][2], a1[mt][3], ad);
                uint32_t ad2 = sA2 + (uint32_t)(mt * 16 * IPAD) + kadd;
                LDMATRIX_X4(a2[mt][0], a2[mt][1], a2[mt][2], a2[mt][3], ad2);
            }
#pragma unroll
            for (int p = 0; p < 2; p++) {          // two 16-n-row pairs
                uint32_t bd = sB1 + (uint32_t)(p * 16 * IPAD) + kadd;
                LDMATRIX_X4(b1[p][0], b1[p][1], b1[p][2], b1[p][3], bd);
                uint32_t bd2 = sB2 + (uint32_t)(p * 16 * IPAD) + kadd;
                LDMATRIX_X4(b2[p][0], b2[p][1], b2[p][2], b2[p][3], bd2);
            }
#pragma unroll
            for (int mt = 0; mt < 4; mt++)
#pragma unroll
                for (int nt = 0; nt < 4; nt++) {
                    int p = nt >> 1, o = nt & 1;   // frag regs {o, o+2} of the x4 pair
                    uint32_t b1f0 = b1[p][o], b1f1 = b1[p][o + 2];
                    uint32_t b2f0 = b2[p][o], b2f1 = b2[p][o + 2];
                    MMA_S8(hi[mt][nt],  a1[mt], b1f0, b1f1);   // P1
                    MMA_S8(mid[mt][nt], a1[mt], b2f0, b2f1);   // P2
                    MMA_S8(mid[mt][nt], a2[mt], b1f0, b1f1);   // P3
                }
        }
        __syncthreads();
    }

    // epilogue: C = sa_i*sb_j*(P1 + (P2+P3)/256)
    int r0 = bm + wm * 64 + (lane >> 2);
    int cc = bn + wn * 32 + (lane & 3) * 2;
#pragma unroll
    for (int mt = 0; mt < 4; mt++) {
        float sar0 = sa[r0 + mt * 16];
        float sar1 = sa[r0 + mt * 16 + 8];
#pragma unroll
        for (int nt = 0; nt < 4; nt++) {
            float sbc0 = sb[cc + nt * 8];
            float sbc1 = sb[cc + nt * 8 + 1];
            const float k = 0.00390625f;  // 1/256
            float v0 = sar0 * sbc0 * ((float)hi[mt][nt][0] + (float)mid[mt][nt][0] * k);
            float v1 = sar0 * sbc1 * ((float)hi[mt][nt][1] + (float)mid[mt][nt][1] * k);
            float v2 = sar1 * sbc0 * ((float)hi[mt][nt][2] + (float)mid[mt][nt][2] * k);
            float v3 = sar1 * sbc1 * ((float)hi[mt][nt][3] + (float)mid[mt][nt][3] * k);
            float* p0 = C + (size_t)(r0 + mt * 16) * N + cc + nt * 8;
            float* p1 = p0 + 8 * N;
            *(float2*)p0 = make_float2(v0, v1);
            *(float2*)p1 = make_float2(v2, v3);
        }
    }
}

// ---------------- fp32 -> int8 2-slice pack (per-row scale) ----------------
__global__ __launch_bounds__(256) void pack_i8(
    const float* __restrict__ src, int8_t* __restrict__ q1,
    int8_t* __restrict__ q2, float* __restrict__ scale, int K) {
    __shared__ float red[256];
    int row = blockIdx.x;
    const float* r = src + (size_t)row * K;
    int n4 = K >> 2;
    float m = 0.f;
    for (int i = threadIdx.x; i < n4; i += 256) {
        float4 v = ((const float4*)r)[i];
        m = fmaxf(m, fmaxf(fmaxf(fabsf(v.x), fabsf(v.y)), fmaxf(fabsf(v.z), fabsf(v.w))));
    }
    red[threadIdx.x] = m;
    __syncthreads();
    for (int o = 128; o; o >>= 1) {
        if (threadIdx.x < o) red[threadIdx.x] = fmaxf(red[threadIdx.x], red[threadIdx.x + o]);
        __syncthreads();
    }
    float s = red[0] * (1.f / 127.f);
    float inv = (s > 0.f) ? 1.f / s : 0.f;
    if (threadIdx.x == 0) scale[row] = s;
    for (int i = threadIdx.x; i < n4; i += 256) {
        float4 v = ((const float4*)r)[i];
        int a0 = __float2int_rn(v.x * inv), a1 = __float2int_rn(v.y * inv);
        int a2 = __float2int_rn(v.z * inv), a3 = __float2int_rn(v.w * inv);
        a0 = max(-127, min(127, a0)); a1 = max(-127, min(127, a1));
        a2 = max(-127, min(127, a2)); a3 = max(-127, min(127, a3));
        int b0 = __float2int_rn((v.x - a0 * s) * inv * 256.f);
        int b1 = __float2int_rn((v.y - a1 * s) * inv * 256.f);
        int b2 = __float2int_rn((v.z - a2 * s) * inv * 256.f);
        int b3 = __float2int_rn((v.w - a3 * s) * inv * 256.f);
        b0 = max(-127, min(127, b0)); b1 = max(-127, min(127, b1));
        b2 = max(-127, min(127, b2)); b3 = max(-127, min(127, b3));
        ((char4*)q1)[(size_t)row * n4 + i] = make_char4((char)a0, (char)a1, (char)a2, (char)a3);
        ((char4*)q2)[(size_t)row * n4 + i] = make_char4((char)b0, (char)b1, (char)b2, (char)b3);
    }
}

// ---------------- pack W_a/W_b into zero-padded [128, HID] fp32 staging ----------------
__global__ __launch_bounds__(256) void pack_ab(
    const float* __restrict__ Wa, const float* __restrict__ Wb) {
    int i = blockIdx.x * 256 + threadIdx.x;        // 128*HID
    if (i >= 128 * HID) return;
    int r = i >> 11;                               // HID = 2048
    float v = 0.f;
    if (r < 32) v = Wa[i];
    else if (r < 64) v = Wb[i - 32 * HID];
    d_ab[i] = v;
}

// ---------------- g/beta from ab projection ----------------
__global__ __launch_bounds__(256) void g_beta(
    const float* __restrict__ dt_bias, const float* __restrict__ A_log) {
    int i = blockIdx.x * 256 + threadIdx.x;        // S_LEN * 64
    int s = i >> 6, j = i & 63;
    float v = d_ab[(size_t)s * 128 + j];
    if (j < 32) {
        float xv = v + dt_bias[j];
        float sp = fmaxf(xv, 0.f) + log1pf(expf(-fabsf(xv)));
        d_g[j * S_LEN + s] = -expf(A_log[j]) * sp;
    } else {
        d_beta[(j - 32) * S_LEN + s] = 1.f / (1.f + expf(-v));
    }
}

// ---------------- per-chunk inclusive cumsum of g ----------------
__global__ void g_cumsum() {
    int h = blockIdx.x >> 5;
    int c = blockIdx.x & 31;
    __shared__ float buf[CHUNK];
    int i = threadIdx.x;
    buf[i] = d_g[h * S_LEN + c * CHUNK + i];
    __syncthreads();
#pragma unroll
    for (int off = 1; off < CHUNK; off <<= 1) {
        float v = (i >= off) ? buf[i - off] : 0.f;
        __syncthreads();
        buf[i] += v;
        __syncthreads();
    }
    d_g[h * S_LEN + c * CHUNK + i] = buf[i];
}

// ---------------- causal depthwise conv (K=4) + SiLU ----------------
__global__ __launch_bounds__(256) void conv_silu(const float* __restrict__ w) {
    int idx = blockIdx.x * 256 + threadIdx.x;
    int c = idx % CONV_DIM;
    int s = idx / CONV_DIM;
    float acc = 0.f;
#pragma unroll
    for (int t = 0; t < KSZ; t++) {
        int sp = s - (KSZ - 1) + t;
        if (sp >= 0) acc += d_mixed[(size_t)sp * CONV_DIM + c] * w[c * KSZ + t];
    }
    d_conv[idx] = acc / (1.f + expf(-acc));
}

// ---------------- l2norm of q,k ----------------
__global__ __launch_bounds__(256) void qk_norm() {
    int gw = (blockIdx.x * 256 + threadIdx.x) >> 5;
    int lane = threadIdx.x & 31;
    int which = gw & 1;
    int hk = (gw >> 1) & (NK - 1);
    int s = gw >> 5;
    const float* src = d_conv + (size_t)s * CONV_DIM + which * KEY_DIM + hk * DK + lane * 4;
    float4 v = *(const float4*)src;
    float ss = v.x * v.x + v.y * v.y + v.z * v.z + v.w * v.w;
#pragma unroll
    for (int o = 16; o; o >>= 1) ss += __shfl_xor_sync(0xffffffffu, ss, o);
    float r = rsqrtf(ss + 1e-6f);
    if (!which) r *= 0.08838834764831845f;
    float* dst = (which ? d_kn : d_qn) + ((size_t)s * NK + hk) * DK + lane * 4;
    v.x *= r; v.y *= r; v.z *= r; v.w *= r;
    *(float4*)dst = v;
}

// ---------------- chunk-local: scores, UT transform, u, kcd ----------------
#define PADK 132
__global__ __launch_bounds__(256) void chunk_kernel() {
    int cid = blockIdx.x;
    int h = blockIdx.y;
    int h2 = h >> 1;
    int s0 = cid * CHUNK;
    extern __shared__ float smf[];
    float* Ks = smf;
    float* KBs = Ks + 64 * PADK;
    float* Qs = KBs + 64 * PADK;
    float* Am = Qs + 64 * PADK;
    float* gc = Am + 64 * 64;
    float* bt = gc + 64;
    float* rowbuf = bt + 64;
    int tid = threadIdx.x;

    if (tid < 64) {
        gc[tid] = d_g[h * S_LEN + s0 + tid];
        bt[tid] = d_beta[h * S_LEN + s0 + tid];
    }
    __syncthreads();

    for (int t = tid; t < 64 * 32; t += 256) {
        int r = t >> 5, c4 = (t & 31) << 2;
        float4 kv = *(const float4*)&d_kn[((size_t)(s0 + r) * NK + h2) * DK + c4];
        float4 qv = *(const float4*)&d_qn[((size_t)(s0 + r) * NK + h2) * DK + c4];
        float b = bt[r];
        Ks[r * PADK + c4 + 0] = kv.x; Ks[r * PADK + c4 + 1] = kv.y;
        Ks[r * PADK + c4 + 2] = kv.z; Ks[r * PADK + c4 + 3] = kv.w;
        Qs[r * PADK + c4 + 0] = qv.x; Qs[r * PADK + c4 + 1] = qv.y;
        Qs[r * PADK + c4 + 2] = qv.z; Qs[r * PADK + c4 + 3] = qv.w;
        KBs[r * PADK + c4 + 0] = kv.x * b; KBs[r * PADK + c4 + 1] = kv.y * b;
        KBs[r * PADK + c4 + 2] = kv.z * b; KBs[r * PADK + c4 + 3] = kv.w * b;
    }
    __syncthreads();

    for (int t = tid; t < 4096; t += 256) {
        int i = t >> 6, j = t & 63;
        float sc = 0.f, am = 0.f;
        if (i >= j) {
            float dq = 0.f, dk = 0.f;
            const float* kr = Ks + j * PADK;
            const float* qr = Qs + i * PADK;
            const float* kbr = KBs + i * PADK;
#pragma unroll 4
            for (int d = 0; d < 128; d++) {
                float kj = kr[d];
                dq += qr[d] * kj;
                dk += kbr[d] * kj;
            }
            float e = expf(gc[i] - gc[j]);
            sc = dq * e;
            if (i > j) am = -dk * e;
        }
        d_scores[(size_t)(h * NCHUNK + cid) * 4096 + t] = sc;
        Am[t] = am;
    }
    __syncthreads();

    for (int i = 1; i < 64; i++) {
        if (tid < i) {
            int j = tid;
            float sum = Am[i * 64 + j];
            for (int k = j + 1; k < i; k++) sum += Am[i * 64 + k] * Am[k * 64 + j];
            rowbuf[j] = sum;
        }
        __syncthreads();
        if (tid < i) Am[i * 64 + tid] = rowbuf[tid];
        __syncthreads();
    }

    if (tid < 64) rowbuf[tid] = expf(gc[tid]);
    __syncthreads();
    for (int t = tid; t < 64 * 128; t += 256) {
        int r = t >> 7, d = t & 127;
        KBs[r * PADK + d] *= rowbuf[r];
    }
    __syncthreads();

    for (int t = tid; t < 8192; t += 256) {
        int i = t >> 7, dk = t & 127;
        float acc = KBs[i * PADK + dk];
        for (int j = 0; j < i; j++) acc += Am[i * 64 + j] * KBs[j * PADK + dk];
        d_kcd[((size_t)h * S_LEN + s0 + i) * DK + dk] = acc;
    }
    __syncthreads();

    for (int t = tid; t < 64 * 32; t += 256) {
        int r = t >> 5, c4 = (t & 31) << 2;
        float4 vv = *(const float4*)&d_conv[(size_t)(s0 + r) * CONV_DIM + 2 * KEY_DIM + h * DV + c4];
        float b = bt[r];
        KBs[r * PADK + c4 + 0] = vv.x * b; KBs[r * PADK + c4 + 1] = vv.y * b;
        KBs[r * PADK + c4 + 2] = vv.z * b; KBs[r * PADK + c4 + 3] = vv.w * b;
    }
    __syncthreads();

    for (int t = tid; t < 8192; t += 256) {
        int i = t >> 7, dv = t & 127;
        float acc = KBs[i * PADK + dv];
        for (int j = 0; j < i; j++) acc += Am[i * 64 + j] * KBs[j * PADK + dv];
        d_u[((size_t)h * S_LEN + s0 + i) * DV + dv] = acc;
    }
}

// ---------------- cross-chunk sequential state scan ----------------
__global__ __launch_bounds__(256) void scan_kernel() {
    int grp = blockIdx.x;
    int h = blockIdx.y;
    int h2 = h >> 1;
    int c0 = grp * 32;
    extern __shared__ float smf[];
    float* state = smf;
    float* T = state + 128 * 33;
    float* vnew = T + 64 * PADK;
    float* sc = vnew + 64 * 33;
    float* gc = sc + 4096;
    int tid = threadIdx.x;

    for (int t = tid; t < 128 * 33; t += 256) state[t] = 0.f;
    __syncthreads();

    for (int cid = 0; cid < NCHUNK; cid++) {
        int s0 = cid * CHUNK;
        if (tid < 64) gc[tid] = d_g[h * S_LEN + s0 + tid];
        __syncthreads();
        float gl = gc[63];

        for (int t = tid; t < 64 * 32; t += 256) {
            int r = t >> 5, c4 = (t & 31) << 2;
            float4 v = *(const float4*)&d_kcd[((size_t)h * S_LEN + s0 + r) * DK + c4];
            T[r * PADK + c4 + 0] = v.x; T[r * PADK + c4 + 1] = v.y;
            T[r * PADK + c4 + 2] = v.z; T[r * PADK + c4 + 3] = v.w;
        }
        __syncthreads();

        for (int t = tid; t < 2048; t += 256) {
            int c = t >> 5, j = t & 31;
            float acc = d_u[((size_t)h * S_LEN + s0 + c) * DV + c0 + j];
            const float* Tr = T + c * PADK;
#pragma unroll 4
            for (int d = 0; d < 128; d++) acc -= Tr[d] * state[d * 33 + j];
            vnew[c * 33 + j] = acc;
        }
        __syncthreads();

        for (int t = tid; t < 64 * 32; t += 256) {
            int r = t >> 5, c4 = (t & 31) << 2;
            float4 v = *(const float4*)&d_qn[((size_t)(s0 + r) * NK + h2) * DK + c4];
            float e = expf(gc[r]);
            T[r * PADK + c4 + 0] = v.x * e; T[r * PADK + c4 + 1] = v.y * e;
            T[r * PADK + c4 + 2] = v.z * e; T[r * PADK + c4 + 3] = v.w * e;
        }
        for (int t = tid; t < 4096; t += 256)
            sc[t] = d_scores[(size_t)(h * NCHUNK + cid) * 4096 + t];
        __syncthreads();

        for (int t = tid; t < 2048; t += 256) {
            int c = t >> 5, j = t & 31;
            float acc = 0.f;
            const float* Tr = T + c * PADK;
#pragma unroll 4
            for (int d = 0; d < 128; d++) acc += Tr[d] * state[d * 33 + j];
            const float* scr = sc + c * 64;
            for (int c2 = 0; c2 <= c; c2++) acc += scr[c2] * vnew[c2 * 33 + j];
            d_o[(size_t)(s0 + c) * VAL_DIM + h * DV + c0 + j] = acc;
        }
        __syncthreads();

        for (int t = tid; t < 64 * 32; t += 256) {
            int r = t >> 5, c4 = (t & 31) << 2;
            float4 v = *(const float4*)&d_kn[((size_t)(s0 + r) * NK + h2) * DK + c4];
            float e = expf(gl - gc[r]);
            T[r * PADK + c4 + 0] = v.x * e; T[r * PADK + c4 + 1] = v.y * e;
            T[r * PADK + c4 + 2] = v.z * e; T[r * PADK + c4 + 3] = v.w * e;
        }
        __syncthreads();

        float egl = expf(gl);
        for (int t = tid; t < 4096; t += 256) {
            int d = t >> 5, j = t & 31;
            float acc = state[d * 33 + j] * egl;
#pragma unroll 4
            for (int c = 0; c < 64; c++) acc += T[c * PADK + d] * vnew[c * 33 + j];
            state[d * 33 + j] = acc;
        }
        __syncthreads();
    }
}

// ---------------- RMS-norm + silu(z) gate -> fp32 h ----------------
__global__ __launch_bounds__(256) void norm_gate(const float* __restrict__ norm_w) {
    int gw = (blockIdx.x * 256 + threadIdx.x) >> 5;
    int lane = threadIdx.x & 31;
    int s = gw >> 5;
    int h = gw & 31;
    size_t base = (size_t)s * VAL_DIM + h * DV + lane * 4;
    float4 v = *(const float4*)(d_o + base);
    float ss = v.x * v.x + v.y * v.y + v.z * v.z + v.w * v.w;
#pragma unroll
    for (int o = 16; o; o >>= 1) ss += __shfl_xor_sync(0xffffffffu, ss, o);
    float r = rsqrtf(ss * (1.f / 128.f) + 1e-6f);
    float4 z = *(const float4*)(d_zbuf + base);
    float4 w = *(const float4*)(norm_w + lane * 4);
    float4 o4;
    o4.x = v.x * r * w.x * (z.x / (1.f + expf(-z.x)));
    o4.y = v.y * r * w.y * (z.y / (1.f + expf(-z.y)));
    o4.z = v.z * r * w.z * (z.z / (1.f + expf(-z.z)));
    o4.w = v.w * r * w.w * (z.w / (1.f + expf(-z.w)));
    *(float4*)(d_hbuf + base) = o4;
}

// ---------------- launch ----------------
extern "C" void kernel_launch(void* const* d_in, const int* in_sizes, int n_in,
                              void* d_out, int out_size) {
    const float* x       = (const float*)d_in[0];
    const float* W_qkv   = (const float*)d_in[1];
    const float* W_z     = (const float*)d_in[2];
    const float* W_a     = (const float*)d_in[3];
    const float* W_b     = (const float*)d_in[4];
    const float* conv_w  = (const float*)d_in[5];
    const float* dt_bias = (const float*)d_in[6];
    const float* A_log   = (const float*)d_in[7];
    const float* norm_w  = (const float*)d_in[8];
    const float* W_out   = (const float*)d_in[9];
    float* out = (float*)d_out;

    void *p_mixed, *p_z, *p_ab, *p_hbuf;
    void *p_x1, *p_x2, *p_sx, *p_wq1, *p_wq2, *p_swq, *p_wz1, *p_wz2, *p_swz;
    void *p_wo1, *p_wo2, *p_swo, *p_h1, *p_h2, *p_sh, *p_wab1, *p_wab2, *p_swab;
    cudaGetSymbolAddress(&p_mixed, d_mixed);
    cudaGetSymbolAddress(&p_z, d_zbuf);
    cudaGetSymbolAddress(&p_ab, d_ab);
    cudaGetSymbolAddress(&p_hbuf, d_hbuf);
    cudaGetSymbolAddress(&p_x1, d_x1);   cudaGetSymbolAddress(&p_x2, d_x2);   cudaGetSymbolAddress(&p_sx, d_sx);
    cudaGetSymbolAddress(&p_wq1, d_wq1); cudaGetSymbolAddress(&p_wq2, d_wq2); cudaGetSymbolAddress(&p_swq, d_swq);
    cudaGetSymbolAddress(&p_wz1, d_wz1); cudaGetSymbolAddress(&p_wz2, d_wz2); cudaGetSymbolAddress(&p_swz, d_swz);
    cudaGetSymbolAddress(&p_wo1, d_wo1); cudaGetSymbolAddress(&p_wo2, d_wo2); cudaGetSymbolAddress(&p_swo, d_swo);
    cudaGetSymbolAddress(&p_h1, d_h1);   cudaGetSymbolAddress(&p_h2, d_h2);   cudaGetSymbolAddress(&p_sh, d_sh);
    cudaGetSymbolAddress(&p_wab1, d_wab1); cudaGetSymbolAddress(&p_wab2, d_wab2); cudaGetSymbolAddress(&p_swab, d_swab);

    int chunk_smem = (3 * 64 * PADK + 64 * 64 + 3 * 64) * (int)sizeof(float);
    int scan_smem  = (128 * 33 + 64 * PADK + 64 * 33 + 64 * 64 + 64) * (int)sizeof(float);
    cudaFuncSetAttribute(chunk_kernel, cudaFuncAttributeMaxDynamicSharedMemorySize, chunk_smem);
    cudaFuncSetAttribute(scan_kernel,  cudaFuncAttributeMaxDynamicSharedMemorySize, scan_smem);
    cudaFuncSetAttribute(gemm_i8,      cudaFuncAttributeMaxDynamicSharedMemorySize, IGEMM_SMEM);

    // int8 2-slice packs
    pack_i8<<<S_LEN, 256>>>(x, (int8_t*)p_x1, (int8_t*)p_x2, (float*)p_sx, HID);
    pack_i8<<<CONV_DIM, 256>>>(W_qkv, (int8_t*)p_wq1, (int8_t*)p_wq2, (float*)p_swq, HID);
    pack_i8<<<VAL_DIM, 256>>>(W_z, (int8_t*)p_wz1, (int8_t*)p_wz2, (float*)p_swz, HID);
    pack_i8<<<HID, 256>>>(W_out, (int8_t*)p_wo1, (int8_t*)p_wo2, (float*)p_swo, VAL_DIM);
    pack_ab<<<(128 * HID + 255) / 256, 256>>>(W_a, W_b);
    pack_i8<<<128, 256>>>((const float*)p_ab, (int8_t*)p_wab1, (int8_t*)p_wab2, (float*)p_swab, HID);

    // projections via int8 tensor-core GEMM
    gemm_i8<<<dim3(CONV_DIM / 128, S_LEN / 128), 256, IGEMM_SMEM>>>(
        (const int8_t*)p_x1, (const int8_t*)p_x2, (const int8_t*)p_wq1, (const int8_t*)p_wq2,
        (const float*)p_sx, (const float*)p_swq, (float*)p_mixed, S_LEN, CONV_DIM, HID);
    gemm_i8<<<dim3(VAL_DIM / 128, S_LEN / 128), 256, IGEMM_SMEM>>>(
        (const int8_t*)p_x1, (const int8_t*)p_x2, (const int8_t*)p_wz1, (const int8_t*)p_wz2,
        (const float*)p_sx, (const float*)p_swz, (float*)p_z, S_LEN, VAL_DIM, HID);
    gemm_i8<<<dim3(1, S_LEN / 128), 256, IGEMM_SMEM>>>(
        (const int8_t*)p_x1, (const int8_t*)p_x2, (const int8_t*)p_wab1, (const int8_t*)p_wab2,
        (const float*)p_sx, (const float*)p_swab, (float*)p_ab, S_LEN, 128, HID);
    g_beta<<<(S_LEN * 64) / 256, 256>>>(dt_bias, A_log);
    g_cumsum<<<NV * NCHUNK, CHUNK>>>();

    conv_silu<<<(S_LEN * CONV_DIM) / 256, 256>>>(conv_w);
    qk_norm<<<(S_LEN * NK * 2) / 8, 256>>>();

    chunk_kernel<<<dim3(NCHUNK, NV), 256, chunk_smem>>>();
    scan_kernel<<<dim3(4, NV), 256, scan_smem>>>();

    norm_gate<<<(S_LEN * NV) / 8, 256>>>(norm_w);
    pack_i8<<<S_LEN, 256>>>((const float*)p_hbuf, (int8_t*)p_h1, (int8_t*)p_h2, (float*)p_sh, VAL_DIM);
    gemm_i8<<<dim3(HID / 128, S_LEN / 128), 256, IGEMM_SMEM>>>(
        (const int8_t*)p_h1, (const int8_t*)p_h2, (const int8_t*)p_wo1, (const int8_t*)p_wo2,
        (const float*)p_sh, (const float*)p_swo, out, S_LEN, HID, VAL_DIM);
}

// round 11
// speedup vs baseline: 1.8550x; 1.5420x over previous
#include <cuda_runtime.h>
#include <cuda_bf16.h>
#include <math.h>
#include <stdint.h>

#define S_LEN 2048
#define HID 2048
#define NK 16
#define NV 32
#define DK 128
#define DV 128
#define KSZ 4
#define CHUNK 64
#define NCHUNK (S_LEN / CHUNK)
#define KEY_DIM (NK * DK)
#define VAL_DIM (NV * DV)
#define CONV_DIM (2 * KEY_DIM + VAL_DIM)

// ---------------- scratch ----------------
__device__ float d_mixed[(size_t)S_LEN * CONV_DIM];
__device__ float d_conv[(size_t)S_LEN * CONV_DIM];
__device__ float d_zbuf[(size_t)S_LEN * VAL_DIM];
__device__ float d_ab[(size_t)S_LEN * 128];
__device__ float d_g[NV * S_LEN];
__device__ float d_beta[NV * S_LEN];
__device__ float d_qn[(size_t)S_LEN * NK * DK];
__device__ float d_kn[(size_t)S_LEN * NK * DK];
__device__ float d_u[(size_t)NV * S_LEN * DV];
__device__ float d_kcd[(size_t)NV * S_LEN * DK];
__device__ float d_scores[(size_t)NV * NCHUNK * CHUNK * CHUNK];
__device__ float d_o[(size_t)S_LEN * VAL_DIM];
__device__ float d_hbuf[(size_t)S_LEN * VAL_DIM];

__device__ int8_t d_x1[(size_t)S_LEN * HID];
__device__ int8_t d_x2[(size_t)S_LEN * HID];
__device__ float  d_sx[S_LEN];
__device__ int8_t d_wq1[(size_t)CONV_DIM * HID];
__device__ int8_t d_wq2[(size_t)CONV_DIM * HID];
__device__ float  d_swq[CONV_DIM];
__device__ int8_t d_wz1[(size_t)VAL_DIM * HID];
__device__ int8_t d_wz2[(size_t)VAL_DIM * HID];
__device__ float  d_swz[VAL_DIM];
__device__ int8_t d_wo1[(size_t)HID * VAL_DIM];
__device__ int8_t d_wo2[(size_t)HID * VAL_DIM];
__device__ float  d_swo[HID];
__device__ int8_t d_h1[(size_t)S_LEN * VAL_DIM];
__device__ int8_t d_h2[(size_t)S_LEN * VAL_DIM];
__device__ float  d_sh[S_LEN];
__device__ int8_t d_wab1[(size_t)128 * HID];
__device__ int8_t d_wab2[(size_t)128 * HID];
__device__ float  d_swab[128];

// ================= helpers =================
__device__ __forceinline__ uint32_t smem_u32_of(const void* p) {
    uint32_t a;
    asm("{ .reg .u64 t; cvta.to.shared.u64 t, %1; cvt.u32.u64 %0, t; }" : "=r"(a) : "l"(p));
    return a;
}

#define LDMATRIX_X4(r0, r1, r2, r3, addr)                                        \
    asm volatile("ldmatrix.sync.aligned.m8n8.x4.shared.b16 {%0,%1,%2,%3}, [%4];" \
                 : "=r"(r0), "=r"(r1), "=r"(r2), "=r"(r3) : "r"(addr))

#define MMA_S8(c, a, b0v, b1v)                                                   \
    asm volatile("mma.sync.aligned.m16n8k32.row.col.s32.s8.s8.s32 "              \
                 "{%0,%1,%2,%3}, {%4,%5,%6,%7}, {%8,%9}, {%0,%1,%2,%3};"         \
                 : "+r"((c)[0]), "+r"((c)[1]), "+r"((c)[2]), "+r"((c)[3])        \
                 : "r"((a)[0]), "r"((a)[1]), "r"((a)[2]), "r"((a)[3]),           \
                   "r"(b0v), "r"(b1v))

// =============== int8 2-slice GEMM, block 128x64 (low reg pressure) ===============
// A ~ sa_i*(A1 + A2/256); B ~ sb_j*(B1 + B2/256).
// C = sa_i*sb_j*(P1 + (P2+P3)/256).  8 warps (2x4), warp tile 64x16, BK=64B, 3-stage.
#define IPAD 80
#define IMAT_A (128 * IPAD)            // 10240 B
#define IMAT_B (64 * IPAD)             // 5120 B
#define ISTAGEB (2 * IMAT_A + 2 * IMAT_B)   // 30720 B
#define INSTAGE 3
#define IGEMM_SMEM (INSTAGE * ISTAGEB)      // 92160 B
#define OFF_A2 IMAT_A
#define OFF_B1 (2 * IMAT_A)
#define OFF_B2 (2 * IMAT_A + IMAT_B)

__device__ __forceinline__ void stage_load_i8(
    uint32_t stage_base,
    const int8_t* __restrict__ A1, const int8_t* __restrict__ A2,
    const int8_t* __restrict__ B1, const int8_t* __restrict__ B2,
    int bm, int bn, int K, int k0, int tid) {
#pragma unroll
    for (int i = 0; i < 6; i++) {
        int id = tid + i * 256;        // 0..1535
        const int8_t* base;
        int row, moff;
        if (id < 512)        { base = A1; row = id >> 2;           moff = 0; }
        else if (id < 1024)  { base = A2; row = (id - 512) >> 2;   moff = OFF_A2; }
        else if (id < 1280)  { base = B1; row = (id - 1024) >> 2;  moff = OFF_B1; }
        else                 { base = B2; row = (id - 1280) >> 2;  moff = OFF_B2; }
        int ch = id & 3;
        int grow = (id < 1024) ? (bm + row) : (bn + row);
        const int8_t* g = base + (size_t)grow * K + k0 + ch * 16;
        uint32_t dst = stage_base + (uint32_t)(moff + row * IPAD + ch * 16);
        asm volatile("cp.async.cg.shared.global [%0], [%1], 16;" :: "r"(dst), "l"(g) : "memory");
    }
    asm volatile("cp.async.commit_group;" ::: "memory");
}

__global__ __launch_bounds__(256, 1)
void gemm_i8(const int8_t* __restrict__ A1, const int8_t* __restrict__ A2,
             const int8_t* __restrict__ B1, const int8_t* __restrict__ B2,
             const float* __restrict__ sa, const float* __restrict__ sb,
             float* __restrict__ C, int M, int N, int K) {
    extern __shared__ char smI[];
    const int tid = threadIdx.x;
    const int lane = tid & 31;
    const int w = tid >> 5;
    const int wm = w >> 2;             // 0..1 -> 64 rows each
    const int wn = w & 3;              // 0..3 -> 16 cols each
    const int bm = blockIdx.y * 128, bn = blockIdx.x * 64;
    const uint32_t smb = smem_u32_of(smI);

    int hi[4][2][4], mid[4][2][4];
#pragma unroll
    for (int mt = 0; mt < 4; mt++)
#pragma unroll
        for (int nt = 0; nt < 2; nt++)
#pragma unroll
            for (int r = 0; r < 4; r++) { hi[mt][nt][r] = 0; mid[mt][nt][r] = 0; }

    const uint32_t aoff = (uint32_t)((wm * 64 + (lane & 15)) * IPAD + (lane >> 4) * 16);
    const uint32_t boff = (uint32_t)((wn * 16 + (lane & 15)) * IPAD + (lane >> 4) * 16);

    const int nkt = K >> 6;
    stage_load_i8(smb, A1, A2, B1, B2, bm, bn, K, 0, tid);
    if (nkt > 1)
        stage_load_i8(smb + ISTAGEB, A1, A2, B1, B2, bm, bn, K, 64, tid);

    for (int kt = 0; kt < nkt; kt++) {
        if (kt + 2 < nkt) {
            int st = (kt + 2) % INSTAGE;
            stage_load_i8(smb + (uint32_t)st * ISTAGEB, A1, A2, B1, B2, bm, bn, K, (kt + 2) * 64, tid);
        }
        if (kt + 3 <= nkt) {
            asm volatile("cp.async.wait_group 2;" ::: "memory");
        } else if (kt + 2 == nkt) {
            asm volatile("cp.async.wait_group 1;" ::: "memory");
        } else {
            asm volatile("cp.async.wait_group 0;" ::: "memory");
        }
        __syncthreads();

        uint32_t sb0 = smb + (uint32_t)(kt % INSTAGE) * ISTAGEB;
        uint32_t sA1 = sb0 + aoff;
        uint32_t sA2 = sb0 + OFF_A2 + aoff;
        uint32_t sB1 = sb0 + OFF_B1 + boff;
        uint32_t sB2 = sb0 + OFF_B2 + boff;

#pragma unroll
        for (int ks = 0; ks < 2; ks++) {
            uint32_t a1[4][4], a2[4][4], b1[4], b2[4];
            uint32_t kadd = (uint32_t)(ks * 32);
#pragma unroll
            for (int mt = 0; mt < 4; mt++) {
                uint32_t ad = sA1 + (uint32_t)(mt * 16 * IPAD) + kadd;
                LDMATRIX_X4(a1[mt][0], a1[mt][1], a1[mt][2], a1[mt][3], ad);
                uint32_t ad2 = sA2 + (uint32_t)(mt * 16 * IPAD) + kadd;
                LDMATRIX_X4(a2[mt][0], a2[mt][1], a2[mt][2], a2[mt][3], ad2);
            }
            LDMATRIX_X4(b1[0], b1[1], b1[2], b1[3], sB1 + kadd);
            LDMATRIX_X4(b2[0], b2[1], b2[2], b2[3], sB2 + kadd);
#pragma unroll
            for (int mt = 0; mt < 4; mt++)
#pragma unroll
                for (int nt = 0; nt < 2; nt++) {
                    uint32_t b1f0 = b1[nt], b1f1 = b1[nt + 2];
                    uint32_t b2f0 = b2[nt], b2f1 = b2[nt + 2];
                    MMA_S8(hi[mt][nt],  a1[mt], b1f0, b1f1);
                    MMA_S8(mid[mt][nt], a1[mt], b2f0, b2f1);
                    MMA_S8(mid[mt][nt], a2[mt], b1f0, b1f1);
                }
        }
        __syncthreads();
    }

    int r0 = bm + wm * 64 + (lane >> 2);
    int cc = bn + wn * 16 + (lane & 3) * 2;
#pragma unroll
    for (int mt = 0; mt < 4; mt++) {
        float sar0 = sa[r0 + mt * 16];
        float sar1 = sa[r0 + mt * 16 + 8];
#pragma unroll
        for (int nt = 0; nt < 2; nt++) {
            float sbc0 = sb[cc + nt * 8];
            float sbc1 = sb[cc + nt * 8 + 1];
            const float kq = 0.00390625f;  // 1/256
            float v0 = sar0 * sbc0 * ((float)hi[mt][nt][0] + (float)mid[mt][nt][0] * kq);
            float v1 = sar0 * sbc1 * ((float)hi[mt][nt][1] + (float)mid[mt][nt][1] * kq);
            float v2 = sar1 * sbc0 * ((float)hi[mt][nt][2] + (float)mid[mt][nt][2] * kq);
            float v3 = sar1 * sbc1 * ((float)hi[mt][nt][3] + (float)mid[mt][nt][3] * kq);
            float* p0 = C + (size_t)(r0 + mt * 16) * N + cc + nt * 8;
            float* p1 = p0 + 8 * N;
            *(float2*)p0 = make_float2(v0, v1);
            *(float2*)p1 = make_float2(v2, v3);
        }
    }
}

// ---------------- fp32 -> int8 2-slice pack ----------------
__global__ __launch_bounds__(256) void pack_i8(
    const float* __restrict__ src, int8_t* __restrict__ q1,
    int8_t* __restrict__ q2, float* __restrict__ scale, int K) {
    __shared__ float red[256];
    int row = blockIdx.x;
    const float* r = src + (size_t)row * K;
    int n4 = K >> 2;
    float m = 0.f;
    for (int i = threadIdx.x; i < n4; i += 256) {
        float4 v = ((const float4*)r)[i];
        m = fmaxf(m, fmaxf(fmaxf(fabsf(v.x), fabsf(v.y)), fmaxf(fabsf(v.z), fabsf(v.w))));
    }
    red[threadIdx.x] = m;
    __syncthreads();
    for (int o = 128; o; o >>= 1) {
        if (threadIdx.x < o) red[threadIdx.x] = fmaxf(red[threadIdx.x], red[threadIdx.x + o]);
        __syncthreads();
    }
    float s = red[0] * (1.f / 127.f);
    float inv = (s > 0.f) ? 1.f / s : 0.f;
    if (threadIdx.x == 0) scale[row] = s;
    for (int i = threadIdx.x; i < n4; i += 256) {
        float4 v = ((const float4*)r)[i];
        int a0 = __float2int_rn(v.x * inv), a1 = __float2int_rn(v.y * inv);
        int a2 = __float2int_rn(v.z * inv), a3 = __float2int_rn(v.w * inv);
        a0 = max(-127, min(127, a0)); a1 = max(-127, min(127, a1));
        a2 = max(-127, min(127, a2)); a3 = max(-127, min(127, a3));
        int b0 = __float2int_rn((v.x - a0 * s) * inv * 256.f);
        int b1 = __float2int_rn((v.y - a1 * s) * inv * 256.f);
        int b2 = __float2int_rn((v.z - a2 * s) * inv * 256.f);
        int b3 = __float2int_rn((v.w - a3 * s) * inv * 256.f);
        b0 = max(-127, min(127, b0)); b1 = max(-127, min(127, b1));
        b2 = max(-127, min(127, b2)); b3 = max(-127, min(127, b3));
        ((char4*)q1)[(size_t)row * n4 + i] = make_char4((char)a0, (char)a1, (char)a2, (char)a3);
        ((char4*)q2)[(size_t)row * n4 + i] = make_char4((char)b0, (char)b1, (char)b2, (char)b3);
    }
}

__global__ __launch_bounds__(256) void pack_ab(
    const float* __restrict__ Wa, const float* __restrict__ Wb) {
    int i = blockIdx.x * 256 + threadIdx.x;
    if (i >= 128 * HID) return;
    int r = i >> 11;
    float v = 0.f;
    if (r < 32) v = Wa[i];
    else if (r < 64) v = Wb[i - 32 * HID];
    d_ab[i] = v;
}

__global__ __launch_bounds__(256) void g_beta(
    const float* __restrict__ dt_bias, const float* __restrict__ A_log) {
    int i = blockIdx.x * 256 + threadIdx.x;
    int s = i >> 6, j = i & 63;
    float v = d_ab[(size_t)s * 128 + j];
    if (j < 32) {
        float xv = v + dt_bias[j];
        float sp = fmaxf(xv, 0.f) + log1pf(expf(-fabsf(xv)));
        d_g[j * S_LEN + s] = -expf(A_log[j]) * sp;
    } else {
        d_beta[(j - 32) * S_LEN + s] = 1.f / (1.f + expf(-v));
    }
}

__global__ void g_cumsum() {
    int h = blockIdx.x >> 5;
    int c = blockIdx.x & 31;
    __shared__ float buf[CHUNK];
    int i = threadIdx.x;
    buf[i] = d_g[h * S_LEN + c * CHUNK + i];
    __syncthreads();
#pragma unroll
    for (int off = 1; off < CHUNK; off <<= 1) {
        float v = (i >= off) ? buf[i - off] : 0.f;
        __syncthreads();
        buf[i] += v;
        __syncthreads();
    }
    d_g[h * S_LEN + c * CHUNK + i] = buf[i];
}

__global__ __launch_bounds__(256) void conv_silu(const float* __restrict__ w) {
    int idx = blockIdx.x * 256 + threadIdx.x;
    int c = idx % CONV_DIM;
    int s = idx / CONV_DIM;
    float acc = 0.f;
#pragma unroll
    for (int t = 0; t < KSZ; t++) {
        int sp = s - (KSZ - 1) + t;
        if (sp >= 0) acc += d_mixed[(size_t)sp * CONV_DIM + c] * w[c * KSZ + t];
    }
    d_conv[idx] = acc / (1.f + expf(-acc));
}

__global__ __launch_bounds__(256) void qk_norm() {
    int gw = (blockIdx.x * 256 + threadIdx.x) >> 5;
    int lane = threadIdx.x & 31;
    int which = gw & 1;
    int hk = (gw >> 1) & (NK - 1);
    int s = gw >> 5;
    const float* src = d_conv + (size_t)s * CONV_DIM + which * KEY_DIM + hk * DK + lane * 4;
    float4 v = *(const float4*)src;
    float ss = v.x * v.x + v.y * v.y + v.z * v.z + v.w * v.w;
#pragma unroll
    for (int o = 16; o; o >>= 1) ss += __shfl_xor_sync(0xffffffffu, ss, o);
    float r = rsqrtf(ss + 1e-6f);
    if (!which) r *= 0.08838834764831845f;
    float* dst = (which ? d_kn : d_qn) + ((size_t)s * NK + hk) * DK + lane * 4;
    v.x *= r; v.y *= r; v.z *= r; v.w *= r;
    *(float4*)dst = v;
}

// ---------------- chunk-local: scores, UT transform, u, kcd (register-tiled) ----------------
#define PADK 132
#define AMS 65
__global__ __launch_bounds__(256) void chunk_kernel() {
    int cid = blockIdx.x;
    int h = blockIdx.y;
    int h2 = h >> 1;
    int s0 = cid * CHUNK;
    extern __shared__ float smf[];
    float* Ks = smf;                   // 64*132
    float* KBs = Ks + 64 * PADK;       // 64*132
    float* Qs = KBs + 64 * PADK;       // 64*132
    float* Am = Qs + 64 * PADK;        // 64*65
    float* gc = Am + 64 * AMS;         // 64
    float* bt = gc + 64;               // 64
    float* rowbuf = bt + 64;           // 64
    int tid = threadIdx.x;

    if (tid < 64) {
        gc[tid] = d_g[h * S_LEN + s0 + tid];
        bt[tid] = d_beta[h * S_LEN + s0 + tid];
    }
    __syncthreads();

    for (int t = tid; t < 64 * 32; t += 256) {
        int r = t >> 5, c4 = (t & 31) << 2;
        float4 kv = *(const float4*)&d_kn[((size_t)(s0 + r) * NK + h2) * DK + c4];
        float4 qv = *(const float4*)&d_qn[((size_t)(s0 + r) * NK + h2) * DK + c4];
        float b = bt[r];
        Ks[r * PADK + c4 + 0] = kv.x; Ks[r * PADK + c4 + 1] = kv.y;
        Ks[r * PADK + c4 + 2] = kv.z; Ks[r * PADK + c4 + 3] = kv.w;
        Qs[r * PADK + c4 + 0] = qv.x; Qs[r * PADK + c4 + 1] = qv.y;
        Qs[r * PADK + c4 + 2] = qv.z; Qs[r * PADK + c4 + 3] = qv.w;
        KBs[r * PADK + c4 + 0] = kv.x * b; KBs[r * PADK + c4 + 1] = kv.y * b;
        KBs[r * PADK + c4 + 2] = kv.z * b; KBs[r * PADK + c4 + 3] = kv.w * b;
    }
    __syncthreads();

    // scores/Am: thread tile 4i x 4j; i = it*4+ii, j = jl + jj*16
    {
        int it = tid >> 4, jl = tid & 15;
        float dq[4][4], dk[4][4];
#pragma unroll
        for (int a = 0; a < 4; a++)
#pragma unroll
            for (int b = 0; b < 4; b++) { dq[a][b] = 0.f; dk[a][b] = 0.f; }
        for (int d = 0; d < 128; d++) {
            float kvv[4];
#pragma unroll
            for (int jj = 0; jj < 4; jj++) kvv[jj] = Ks[(jl + jj * 16) * PADK + d];
#pragma unroll
            for (int ii = 0; ii < 4; ii++) {
                float qv = Qs[(it * 4 + ii) * PADK + d];
                float kbv = KBs[(it * 4 + ii) * PADK + d];
#pragma unroll
                for (int jj = 0; jj < 4; jj++) {
                    dq[ii][jj] += qv * kvv[jj];
                    dk[ii][jj] += kbv * kvv[jj];
                }
            }
        }
        size_t sbase = (size_t)(h * NCHUNK + cid) * 4096;
#pragma unroll
        for (int ii = 0; ii < 4; ii++) {
            int i = it * 4 + ii;
#pragma unroll
            for (int jj = 0; jj < 4; jj++) {
                int j = jl + jj * 16;
                float scv = 0.f, amv = 0.f;
                if (i >= j) {
                    float e = expf(gc[i] - gc[j]);
                    scv = dq[ii][jj] * e;
                    if (i > j) amv = -dk[ii][jj] * e;
                }
                d_scores[sbase + i * 64 + j] = scv;
                Am[i * AMS + j] = amv;
            }
        }
    }
    __syncthreads();

    // UT transform (forward substitution)
    for (int i = 1; i < 64; i++) {
        if (tid < i) {
            int j = tid;
            float sum = Am[i * AMS + j];
            for (int k = j + 1; k < i; k++) sum += Am[i * AMS + k] * Am[k * AMS + j];
            rowbuf[j] = sum;
        }
        __syncthreads();
        if (tid < i) Am[i * AMS + tid] = rowbuf[tid];
        __syncthreads();
    }

    if (tid < 64) rowbuf[tid] = expf(gc[tid]);
    __syncthreads();
    for (int t = tid; t < 64 * 128; t += 256) {
        int r = t >> 7, d = t & 127;
        KBs[r * PADK + d] *= rowbuf[r];
    }
    __syncthreads();

    // kcd = (Am + I) @ (kb*exp(g)) : thread = 2 rows x 16 cols (4 x float4, 32-stride)
    {
        int i2 = (tid >> 3) * 2;
        int dkl = (tid & 7) * 4;
        float4 acc0[4], acc1[4];
#pragma unroll
        for (int q = 0; q < 4; q++) {
            acc0[q] = *(float4*)&KBs[i2 * PADK + dkl + 32 * q];
            acc1[q] = *(float4*)&KBs[(i2 + 1) * PADK + dkl + 32 * q];
        }
        for (int j = 0; j < i2; j++) {
            float a0 = Am[i2 * AMS + j], a1 = Am[(i2 + 1) * AMS + j];
#pragma unroll
            for (int q = 0; q < 4; q++) {
                float4 kb = *(float4*)&KBs[j * PADK + dkl + 32 * q];
                acc0[q].x += a0 * kb.x; acc0[q].y += a0 * kb.y; acc0[q].z += a0 * kb.z; acc0[q].w += a0 * kb.w;
                acc1[q].x += a1 * kb.x; acc1[q].y += a1 * kb.y; acc1[q].z += a1 * kb.z; acc1[q].w += a1 * kb.w;
            }
        }
        {
            float a1 = Am[(i2 + 1) * AMS + i2];
#pragma unroll
            for (int q = 0; q < 4; q++) {
                float4 kb = *(float4*)&KBs[i2 * PADK + dkl + 32 * q];
                acc1[q].x += a1 * kb.x; acc1[q].y += a1 * kb.y; acc1[q].z += a1 * kb.z; acc1[q].w += a1 * kb.w;
            }
        }
#pragma unroll
        for (int q = 0; q < 4; q++) {
            *(float4*)&d_kcd[((size_t)h * S_LEN + s0 + i2) * DK + dkl + 32 * q] = acc0[q];
            *(float4*)&d_kcd[((size_t)h * S_LEN + s0 + i2 + 1) * DK + dkl + 32 * q] = acc1[q];
        }
    }
    __syncthreads();

    // overwrite KBs with v*beta
    for (int t = tid; t < 64 * 32; t += 256) {
        int r = t >> 5, c4 = (t & 31) << 2;
        float4 vv = *(const float4*)&d_conv[(size_t)(s0 + r) * CONV_DIM + 2 * KEY_DIM + h * DV + c4];
        float b = bt[r];
        KBs[r * PADK + c4 + 0] = vv.x * b; KBs[r * PADK + c4 + 1] = vv.y * b;
        KBs[r * PADK + c4 + 2] = vv.z * b; KBs[r * PADK + c4 + 3] = vv.w * b;
    }
    __syncthreads();

    // u = (Am + I) @ (v*beta)
    {
        int i2 = (tid >> 3) * 2;
        int dkl = (tid & 7) * 4;
        float4 acc0[4], acc1[4];
#pragma unroll
        for (int q = 0; q < 4; q++) {
            acc0[q] = *(float4*)&KBs[i2 * PADK + dkl + 32 * q];
            acc1[q] = *(float4*)&KBs[(i2 + 1) * PADK + dkl + 32 * q];
        }
        for (int j = 0; j < i2; j++) {
            float a0 = Am[i2 * AMS + j], a1 = Am[(i2 + 1) * AMS + j];
#pragma unroll
            for (int q = 0; q < 4; q++) {
                float4 kb = *(float4*)&KBs[j * PADK + dkl + 32 * q];
                acc0[q].x += a0 * kb.x; acc0[q].y += a0 * kb.y; acc0[q].z += a0 * kb.z; acc0[q].w += a0 * kb.w;
                acc1[q].x += a1 * kb.x; acc1[q].y += a1 * kb.y; acc1[q].z += a1 * kb.z; acc1[q].w += a1 * kb.w;
            }
        }
        {
            float a1 = Am[(i2 + 1) * AMS + i2];
#pragma unroll
            for (int q = 0; q < 4; q++) {
                float4 kb = *(float4*)&KBs[i2 * PADK + dkl + 32 * q];
                acc1[q].x += a1 * kb.x; acc1[q].y += a1 * kb.y; acc1[q].z += a1 * kb.z; acc1[q].w += a1 * kb.w;
            }
        }
#pragma unroll
        for (int q = 0; q < 4; q++) {
            *(float4*)&d_u[((size_t)h * S_LEN + s0 + i2) * DV + dkl + 32 * q] = acc0[q];
            *(float4*)&d_u[((size_t)h * S_LEN + s0 + i2 + 1) * DV + dkl + 32 * q] = acc1[q];
        }
    }
}

// ---------------- cross-chunk state scan (register-tiled) ----------------
#define SST 36
__global__ __launch_bounds__(256) void scan_kernel() {
    int grp = blockIdx.x;
    int h = blockIdx.y;
    int h2 = h >> 1;
    int colbase = grp * 32;
    extern __shared__ float smf[];
    float* state = smf;                // 128*36
    float* T = state + 128 * SST;      // 64*132
    float* vnew = T + 64 * PADK;       // 64*36
    float* sc = vnew + 64 * SST;       // 64*64
    float* gc = sc + 4096;             // 64
    int tid = threadIdx.x;
    int c0t = (tid >> 3) * 2;          // row pair for c-tiled loops
    int jb = (tid & 7) * 4;            // 4 cols

    for (int t = tid; t < 128 * SST; t += 256) state[t] = 0.f;
    __syncthreads();

    for (int cid = 0; cid < NCHUNK; cid++) {
        int s0 = cid * CHUNK;
        if (tid < 64) gc[tid] = d_g[h * S_LEN + s0 + tid];
        __syncthreads();
        float gl = gc[63];

        // T <- kcd tile
        for (int t = tid; t < 64 * 32; t += 256) {
            int r = t >> 5, c4 = (t & 31) << 2;
            float4 v = *(const float4*)&d_kcd[((size_t)h * S_LEN + s0 + r) * DK + c4];
            T[r * PADK + c4 + 0] = v.x; T[r * PADK + c4 + 1] = v.y;
            T[r * PADK + c4 + 2] = v.z; T[r * PADK + c4 + 3] = v.w;
        }
        __syncthreads();

        // vnew = u - kcd @ state   (2 rows x 4 cols per thread)
        {
            float4 a0 = *(const float4*)&d_u[((size_t)h * S_LEN + s0 + c0t) * DV + colbase + jb];
            float4 a1 = *(const float4*)&d_u[((size_t)h * S_LEN + s0 + c0t + 1) * DV + colbase + jb];
            for (int d = 0; d < 128; d++) {
                float t0 = T[c0t * PADK + d];
                float t1 = T[(c0t + 1) * PADK + d];
                float4 sv = *(float4*)&state[d * SST + jb];
                a0.x -= t0 * sv.x; a0.y -= t0 * sv.y; a0.z -= t0 * sv.z; a0.w -= t0 * sv.w;
                a1.x -= t1 * sv.x; a1.y -= t1 * sv.y; a1.z -= t1 * sv.z; a1.w -= t1 * sv.w;
            }
            *(float4*)&vnew[c0t * SST + jb] = a0;
            *(float4*)&vnew[(c0t + 1) * SST + jb] = a1;
        }
        __syncthreads();

        // T <- q*exp(gc); sc <- scores
        for (int t = tid; t < 64 * 32; t += 256) {
            int r = t >> 5, c4 = (t & 31) << 2;
            float4 v = *(const float4*)&d_qn[((size_t)(s0 + r) * NK + h2) * DK + c4];
            float e = expf(gc[r]);
            T[r * PADK + c4 + 0] = v.x * e; T[r * PADK + c4 + 1] = v.y * e;
            T[r * PADK + c4 + 2] = v.z * e; T[r * PADK + c4 + 3] = v.w * e;
        }
        for (int t = tid; t < 4096; t += 256)
            sc[t] = d_scores[(size_t)(h * NCHUNK + cid) * 4096 + t];
        __syncthreads();

        // o = (q*exp(g)) @ state + scores @ vnew
        {
            float4 a0 = make_float4(0.f, 0.f, 0.f, 0.f);
            float4 a1 = make_float4(0.f, 0.f, 0.f, 0.f);
            for (int d = 0; d < 128; d++) {
                float t0 = T[c0t * PADK + d];
                float t1 = T[(c0t + 1) * PADK + d];
                float4 sv = *(float4*)&state[d * SST + jb];
                a0.x += t0 * sv.x; a0.y += t0 * sv.y; a0.z += t0 * sv.z; a0.w += t0 * sv.w;
                a1.x += t1 * sv.x; a1.y += t1 * sv.y; a1.z += t1 * sv.z; a1.w += t1 * sv.w;
            }
            for (int c2 = 0; c2 <= c0t; c2++) {
                float s0v = sc[c0t * 64 + c2];
                float s1v = sc[(c0t + 1) * 64 + c2];
                float4 vv = *(float4*)&vnew[c2 * SST + jb];
                a0.x += s0v * vv.x; a0.y += s0v * vv.y; a0.z += s0v * vv.z; a0.w += s0v * vv.w;
                a1.x += s1v * vv.x; a1.y += s1v * vv.y; a1.z += s1v * vv.z; a1.w += s1v * vv.w;
            }
            {
                float s1v = sc[(c0t + 1) * 64 + c0t + 1];
                float4 vv = *(float4*)&vnew[(c0t + 1) * SST + jb];
                a1.x += s1v * vv.x; a1.y += s1v * vv.y; a1.z += s1v * vv.z; a1.w += s1v * vv.w;
            }
            *(float4*)&d_o[(size_t)(s0 + c0t) * VAL_DIM + h * DV + colbase + jb] = a0;
            *(float4*)&d_o[(size_t)(s0 + c0t + 1) * VAL_DIM + h * DV + colbase + jb] = a1;
        }
        __syncthreads();

        // T <- k*exp(gl-gc)
        for (int t = tid; t < 64 * 32; t += 256) {
            int r = t >> 5, c4 = (t & 31) << 2;
            float4 v = *(const float4*)&d_kn[((size_t)(s0 + r) * NK + h2) * DK + c4];
            float e = expf(gl - gc[r]);
            T[r * PADK + c4 + 0] = v.x * e; T[r * PADK + c4 + 1] = v.y * e;
            T[r * PADK + c4 + 2] = v.z * e; T[r * PADK + c4 + 3] = v.w * e;
        }
        __syncthreads();

        // state = state*exp(gl) + (k*exp(gl-g))^T @ vnew   (4 d-rows x 4 cols per thread)
        {
            int db = (tid >> 3) * 4;
            float egl = expf(gl);
            float4 f0 = *(float4*)&state[(db + 0) * SST + jb];
            float4 f1 = *(float4*)&state[(db + 1) * SST + jb];
            float4 f2 = *(float4*)&state[(db + 2) * SST + jb];
            float4 f3 = *(float4*)&state[(db + 3) * SST + jb];
            f0.x *= egl; f0.y *= egl; f0.z *= egl; f0.w *= egl;
            f1.x *= egl; f1.y *= egl; f1.z *= egl; f1.w *= egl;
            f2.x *= egl; f2.y *= egl; f2.z *= egl; f2.w *= egl;
            f3.x *= egl; f3.y *= egl; f3.z *= egl; f3.w *= egl;
            for (int c = 0; c < 64; c++) {
                float4 tv = *(float4*)&T[c * PADK + db];
                float4 vv = *(float4*)&vnew[c * SST + jb];
                f0.x += tv.x * vv.x; f0.y += tv.x * vv.y; f0.z += tv.x * vv.z; f0.w += tv.x * vv.w;
                f1.x += tv.y * vv.x; f1.y += tv.y * vv.y; f1.z += tv.y * vv.z; f1.w += tv.y * vv.w;
                f2.x += tv.z * vv.x; f2.y += tv.z * vv.y; f2.z += tv.z * vv.z; f2.w += tv.z * vv.w;
                f3.x += tv.w * vv.x; f3.y += tv.w * vv.y; f3.z += tv.w * vv.z; f3.w += tv.w * vv.w;
            }
            __syncthreads();
            *(float4*)&state[(db + 0) * SST + jb] = f0;
            *(float4*)&state[(db + 1) * SST + jb] = f1;
            *(float4*)&state[(db + 2) * SST + jb] = f2;
            *(float4*)&state[(db + 3) * SST + jb] = f3;
        }
        __syncthreads();
    }
}

// ---------------- RMS-norm + silu(z) gate ----------------
__global__ __launch_bounds__(256) void norm_gate(const float* __restrict__ norm_w) {
    int gw = (blockIdx.x * 256 + threadIdx.x) >> 5;
    int lane = threadIdx.x & 31;
    int s = gw >> 5;
    int h = gw & 31;
    size_t base = (size_t)s * VAL_DIM + h * DV + lane * 4;
    float4 v = *(const float4*)(d_o + base);
    float ss = v.x * v.x + v.y * v.y + v.z * v.z + v.w * v.w;
#pragma unroll
    for (int o = 16; o; o >>= 1) ss += __shfl_xor_sync(0xffffffffu, ss, o);
    float r = rsqrtf(ss * (1.f / 128.f) + 1e-6f);
    float4 z = *(const float4*)(d_zbuf + base);
    float4 w = *(const float4*)(norm_w + lane * 4);
    float4 o4;
    o4.x = v.x * r * w.x * (z.x / (1.f + expf(-z.x)));
    o4.y = v.y * r * w.y * (z.y / (1.f + expf(-z.y)));
    o4.z = v.z * r * w.z * (z.z / (1.f + expf(-z.z)));
    o4.w = v.w * r * w.w * (z.w / (1.f + expf(-z.w)));
    *(float4*)(d_hbuf + base) = o4;
}

// ---------------- launch ----------------
extern "C" void kernel_launch(void* const* d_in, const int* in_sizes, int n_in,
                              void* d_out, int out_size) {
    const float* x       = (const float*)d_in[0];
    const float* W_qkv   = (const float*)d_in[1];
    const float* W_z     = (const float*)d_in[2];
    const float* W_a     = (const float*)d_in[3];
    const float* W_b     = (const float*)d_in[4];
    const float* conv_w  = (const float*)d_in[5];
    const float* dt_bias = (const float*)d_in[6];
    const float* A_log   = (const float*)d_in[7];
    const float* norm_w  = (const float*)d_in[8];
    const float* W_out   = (const float*)d_in[9];
    float* out = (float*)d_out;

    void *p_mixed, *p_z, *p_ab, *p_hbuf;
    void *p_x1, *p_x2, *p_sx, *p_wq1, *p_wq2, *p_swq, *p_wz1, *p_wz2, *p_swz;
    void *p_wo1, *p_wo2, *p_swo, *p_h1, *p_h2, *p_sh, *p_wab1, *p_wab2, *p_swab;
    cudaGetSymbolAddress(&p_mixed, d_mixed);
    cudaGetSymbolAddress(&p_z, d_zbuf);
    cudaGetSymbolAddress(&p_ab, d_ab);
    cudaGetSymbolAddress(&p_hbuf, d_hbuf);
    cudaGetSymbolAddress(&p_x1, d_x1);   cudaGetSymbolAddress(&p_x2, d_x2);   cudaGetSymbolAddress(&p_sx, d_sx);
    cudaGetSymbolAddress(&p_wq1, d_wq1); cudaGetSymbolAddress(&p_wq2, d_wq2); cudaGetSymbolAddress(&p_swq, d_swq);
    cudaGetSymbolAddress(&p_wz1, d_wz1); cudaGetSymbolAddress(&p_wz2, d_wz2); cudaGetSymbolAddress(&p_swz, d_swz);
    cudaGetSymbolAddress(&p_wo1, d_wo1); cudaGetSymbolAddress(&p_wo2, d_wo2); cudaGetSymbolAddress(&p_swo, d_swo);
    cudaGetSymbolAddress(&p_h1, d_h1);   cudaGetSymbolAddress(&p_h2, d_h2);   cudaGetSymbolAddress(&p_sh, d_sh);
    cudaGetSymbolAddress(&p_wab1, d_wab1); cudaGetSymbolAddress(&p_wab2, d_wab2); cudaGetSymbolAddress(&p_swab, d_swab);

    int chunk_smem = (3 * 64 * PADK + 64 * AMS + 3 * 64) * (int)sizeof(float);
    int scan_smem  = (128 * SST + 64 * PADK + 64 * SST + 64 * 64 + 64) * (int)sizeof(float);
    cudaFuncSetAttribute(chunk_kernel, cudaFuncAttributeMaxDynamicSharedMemorySize, chunk_smem);
    cudaFuncSetAttribute(scan_kernel,  cudaFuncAttributeMaxDynamicSharedMemorySize, scan_smem);
    cudaFuncSetAttribute(gemm_i8,      cudaFuncAttributeMaxDynamicSharedMemorySize, IGEMM_SMEM);

    pack_i8<<<S_LEN, 256>>>(x, (int8_t*)p_x1, (int8_t*)p_x2, (float*)p_sx, HID);
    pack_i8<<<CONV_DIM, 256>>>(W_qkv, (int8_t*)p_wq1, (int8_t*)p_wq2, (float*)p_swq, HID);
    pack_i8<<<VAL_DIM, 256>>>(W_z, (int8_t*)p_wz1, (int8_t*)p_wz2, (float*)p_swz, HID);
    pack_i8<<<HID, 256>>>(W_out, (int8_t*)p_wo1, (int8_t*)p_wo2, (float*)p_swo, VAL_DIM);
    pack_ab<<<(128 * HID + 255) / 256, 256>>>(W_a, W_b);
    pack_i8<<<128, 256>>>((const float*)p_ab, (int8_t*)p_wab1, (int8_t*)p_wab2, (float*)p_swab, HID);

    gemm_i8<<<dim3(CONV_DIM / 64, S_LEN / 128), 256, IGEMM_SMEM>>>(
        (const int8_t*)p_x1, (const int8_t*)p_x2, (const int8_t*)p_wq1, (const int8_t*)p_wq2,
        (const float*)p_sx, (const float*)p_swq, (float*)p_mixed, S_LEN, CONV_DIM, HID);
    gemm_i8<<<dim3(VAL_DIM / 64, S_LEN / 128), 256, IGEMM_SMEM>>>(
        (const int8_t*)p_x1, (const int8_t*)p_x2, (const int8_t*)p_wz1, (const int8_t*)p_wz2,
        (const float*)p_sx, (const float*)p_swz, (float*)p_z, S_LEN, VAL_DIM, HID);
    gemm_i8<<<dim3(2, S_LEN / 128), 256, IGEMM_SMEM>>>(
        (const int8_t*)p_x1, (const int8_t*)p_x2, (const int8_t*)p_wab1, (const int8_t*)p_wab2,
        (const float*)p_sx, (const float*)p_swab, (float*)p_ab, S_LEN, 128, HID);
    g_beta<<<(S_LEN * 64) / 256, 256>>>(dt_bias, A_log);
    g_cumsum<<<NV * NCHUNK, CHUNK>>>();

    conv_silu<<<(S_LEN * CONV_DIM) / 256, 256>>>(conv_w);
    qk_norm<<<(S_LEN * NK * 2) / 8, 256>>>();

    chunk_kernel<<<dim3(NCHUNK, NV), 256, chunk_smem>>>();
    scan_kernel<<<dim3(4, NV), 256, scan_smem>>>();

    norm_gate<<<(S_LEN * NV) / 8, 256>>>(norm_w);
    pack_i8<<<S_LEN, 256>>>((const float*)p_hbuf, (int8_t*)p_h1, (int8_t*)p_h2, (float*)p_sh, VAL_DIM);
    gemm_i8<<<dim3(HID / 64, S_LEN / 128), 256, IGEMM_SMEM>>>(
        (const int8_t*)p_h1, (const int8_t*)p_h2, (const int8_t*)p_wo1, (const int8_t*)p_wo2,
        (const float*)p_sh, (const float*)p_swo, out, S_LEN, HID, VAL_DIM);
}